// round 5
// baseline (speedup 1.0000x reference)
#include <cuda_runtime.h>
#include <stdint.h>

#define NB 4
#define SEQ 2048
#define CH 512
#define NH 8
#define HD 64
#define SCALE 0.125f
// SCALE * log2(e)
#define SC2 0.18033688011112042f

// ---------------- device scratch (allocation-free rule: static globals) ----------------
__device__ float g_Q[(size_t)NB * NH * SEQ * HD];
__device__ float g_K[(size_t)NB * NH * SEQ * HD];
__device__ float g_V[(size_t)NB * NH * SEQ * HD];
__device__ float g_attn[(size_t)NB * SEQ * CH];

// ---------------- helpers ---------------------------------------------------------------
__device__ __forceinline__ uint32_t f2tf(float f) {
    uint32_t r;
    asm("cvt.rna.tf32.f32 %0, %1;" : "=r"(r) : "f"(f));
    return r;
}

__device__ __forceinline__ float ex2(float x) {
    float r;
    asm("ex2.approx.ftz.f32 %0, %1;" : "=f"(r) : "f"(x));
    return r;
}

__device__ __forceinline__ float frcp(float x) {
    float r;
    asm("rcp.approx.ftz.f32 %0, %1;" : "=f"(r) : "f"(x));
    return r;
}

__device__ __forceinline__ void mma8(float& d0, float& d1, float& d2, float& d3,
                                     uint32_t a0, uint32_t a1, uint32_t a2, uint32_t a3,
                                     uint32_t b0, uint32_t b1) {
    asm volatile(
        "mma.sync.aligned.m16n8k8.row.col.f32.tf32.tf32.f32 "
        "{%0,%1,%2,%3},{%4,%5,%6,%7},{%8,%9},{%0,%1,%2,%3};"
        : "+f"(d0), "+f"(d1), "+f"(d2), "+f"(d3)
        : "r"(a0), "r"(a1), "r"(a2), "r"(a3), "r"(b0), "r"(b1));
}

// ---------------- JAX threefry2x32, partitionable: bits for flat index ------------------
__device__ __forceinline__ uint32_t tf_bits(uint32_t idx) {
    const uint32_t ks0 = 0u, ks1 = 42u, ks2 = 0x1BD11BF0u;
    uint32_t x0 = ks0;
    uint32_t x1 = idx + ks1;
#define TF_R(r) { x0 += x1; x1 = __funnelshift_l(x1, x1, (r)); x1 ^= x0; }
    TF_R(13) TF_R(15) TF_R(26) TF_R(6)   x0 += ks1; x1 += ks2 + 1u;
    TF_R(17) TF_R(29) TF_R(16) TF_R(24)  x0 += ks2; x1 += ks0 + 2u;
    TF_R(13) TF_R(15) TF_R(26) TF_R(6)   x0 += ks0; x1 += ks1 + 3u;
    TF_R(17) TF_R(29) TF_R(16) TF_R(24)  x0 += ks1; x1 += ks2 + 4u;
    TF_R(13) TF_R(15) TF_R(26) TF_R(6)   x0 += ks2; x1 += ks0 + 5u;
#undef TF_R
    return x0 ^ x1;
}

// ---------------- hybrid -log(u): MUFU lg2 fast path + exact series near u->1 ----------
__device__ __forceinline__ float neglog_u(uint32_t bits) {
    float v = __uint_as_float((bits >> 9) | 0x3f800000u);  // [1,2)
    float u = v - 1.0f;                                    // exact
    float l;
    asm("lg2.approx.ftz.f32 %0, %1;" : "=f"(l) : "f"(u));
    float t1 = -0.6931471805599453f * l;
    float d = 2.0f - v;                                    // = 1-u, exact
    float t2 = d * fmaf(d, fmaf(d, 0.3333333333f, 0.5f), 1.0f);
    return (d < 0.0078125f) ? t2 : t1;
}

// ---------------- projection GEMM body: 64x64 tile, BK=32, double-buffered -------------
// k-pair interleaved smem (ld=40): within each 8-col block, position p holds k-offset
// (p&1) ? (p>>1)+4 : (p>>1), so the mma fragment pair (tig, tig+4) is one LDS.64.
template <bool HEADSPLIT>
__device__ __forceinline__ void proj_body(
    const float* __restrict__ Xb, const float* __restrict__ W,
    const float* __restrict__ bias, float* __restrict__ out,
    int b, int n0, int j0)
{
    __shared__ uint32_t smem[10240];          // As[2][64*40] + Ws[2][64*40] = 40 KB
    const int t = threadIdx.x;
    const int w = t >> 5, lane = t & 31;
    const int wm = w & 1, wn = w >> 1;        // 2(m) x 4(n) warp grid, warp tile 32x16
    const int g = lane >> 2, tig = lane & 3;
    const int rs = t >> 2, b8 = (t & 3) * 8;  // staging chunk: row rs, 8 k-values

    float acc[2][2][4] = {};

    const float* Arow = &Xb[(size_t)(n0 + rs) * CH + b8];
    const float* Wrow = &W[(size_t)(j0 + rs) * CH + b8];

    float4 fa0 = *(const float4*)(Arow);
    float4 fa1 = *(const float4*)(Arow + 4);
    float4 fw0 = *(const float4*)(Wrow);
    float4 fw1 = *(const float4*)(Wrow + 4);

    #pragma unroll 2
    for (int kk = 0; kk < 16; kk++) {
        uint32_t* Ab = smem + (kk & 1) * 2560;
        uint32_t* Wb = smem + 5120 + (kk & 1) * 2560;
        // store staged chunk (interleaved k-pairs) into this step's buffer
        uint4 s;
        s.x = f2tf(fa0.x); s.y = f2tf(fa1.x); s.z = f2tf(fa0.y); s.w = f2tf(fa1.y);
        *(uint4*)&Ab[rs * 40 + b8] = s;
        s.x = f2tf(fa0.z); s.y = f2tf(fa1.z); s.z = f2tf(fa0.w); s.w = f2tf(fa1.w);
        *(uint4*)&Ab[rs * 40 + b8 + 4] = s;
        s.x = f2tf(fw0.x); s.y = f2tf(fw1.x); s.z = f2tf(fw0.y); s.w = f2tf(fw1.y);
        *(uint4*)&Wb[rs * 40 + b8] = s;
        s.x = f2tf(fw0.z); s.y = f2tf(fw1.z); s.z = f2tf(fw0.w); s.w = f2tf(fw1.w);
        *(uint4*)&Wb[rs * 40 + b8 + 4] = s;
        __syncthreads();
        // prefetch next k-step while this step's mma runs
        if (kk + 1 < 16) {
            const float* an = Arow + (kk + 1) * 32;
            const float* wn_ = Wrow + (kk + 1) * 32;
            fa0 = *(const float4*)(an);
            fa1 = *(const float4*)(an + 4);
            fw0 = *(const float4*)(wn_);
            fw1 = *(const float4*)(wn_ + 4);
        }
        #pragma unroll
        for (int ks = 0; ks < 4; ks++) {
            const int kb = ks * 8 + 2 * tig;
            uint2 aL0 = *(uint2*)&Ab[(wm * 32 + g) * 40 + kb];        // (a0, a2) rows g
            uint2 aL1 = *(uint2*)&Ab[(wm * 32 + g + 8) * 40 + kb];    // (a1, a3)
            uint2 aL2 = *(uint2*)&Ab[(wm * 32 + 16 + g) * 40 + kb];
            uint2 aL3 = *(uint2*)&Ab[(wm * 32 + 16 + g + 8) * 40 + kb];
            uint2 bL0 = *(uint2*)&Wb[(wn * 16 + g) * 40 + kb];        // (b0, b1)
            uint2 bL1 = *(uint2*)&Wb[(wn * 16 + 8 + g) * 40 + kb];
            mma8(acc[0][0][0], acc[0][0][1], acc[0][0][2], acc[0][0][3],
                 aL0.x, aL1.x, aL0.y, aL1.y, bL0.x, bL0.y);
            mma8(acc[0][1][0], acc[0][1][1], acc[0][1][2], acc[0][1][3],
                 aL0.x, aL1.x, aL0.y, aL1.y, bL1.x, bL1.y);
            mma8(acc[1][0][0], acc[1][0][1], acc[1][0][2], acc[1][0][3],
                 aL2.x, aL3.x, aL2.y, aL3.y, bL0.x, bL0.y);
            mma8(acc[1][1][0], acc[1][1][1], acc[1][1][2], acc[1][1][3],
                 aL2.x, aL3.x, aL2.y, aL3.y, bL1.x, bL1.y);
        }
    }

    #pragma unroll
    for (int mt = 0; mt < 2; mt++) {
        int n = n0 + wm * 32 + mt * 16 + g;
        #pragma unroll
        for (int nt = 0; nt < 2; nt++) {
            int j = j0 + wn * 16 + nt * 8 + 2 * tig;
            float2 bj = *(const float2*)&bias[j];
            float2 v0 = make_float2(acc[mt][nt][0] + bj.x, acc[mt][nt][1] + bj.y);
            float2 v1 = make_float2(acc[mt][nt][2] + bj.x, acc[mt][nt][3] + bj.y);
            if (HEADSPLIT) {
                size_t base = (((size_t)b * NH + (j >> 6)) * SEQ) * HD + (j & 63);
                *(float2*)&out[base + (size_t)n * HD]       = v0;
                *(float2*)&out[base + (size_t)(n + 8) * HD] = v1;
            } else {
                *(float2*)&out[((size_t)b * SEQ + n) * CH + j]     = v0;
                *(float2*)&out[((size_t)b * SEQ + n + 8) * CH + j] = v1;
            }
        }
    }
}

__global__ __launch_bounds__(256, 3) void proj_qkv(
    const float* __restrict__ x, const float* __restrict__ y, const float* __restrict__ z,
    const float* __restrict__ Wq, const float* __restrict__ bq,
    const float* __restrict__ Wk, const float* __restrict__ bk,
    const float* __restrict__ Wv, const float* __restrict__ bv,
    float* __restrict__ oq, float* __restrict__ ok, float* __restrict__ ov)
{
    const int b     = blockIdx.z & 3;
    const int which = blockIdx.z >> 2;
    const float* X    = (which == 0) ? x  : (which == 1) ? y  : z;
    const float* W    = (which == 0) ? Wq : (which == 1) ? Wk : Wv;
    const float* bias = (which == 0) ? bq : (which == 1) ? bk : bv;
    float* out        = (which == 0) ? oq : (which == 1) ? ok : ov;
    proj_body<true>(X + (size_t)b * SEQ * CH, W, bias, out, b,
                    blockIdx.x * 64, blockIdx.y * 64);
}

__global__ __launch_bounds__(256, 3) void proj_out_k(
    const float* __restrict__ X, const float* __restrict__ W,
    const float* __restrict__ bias, float* __restrict__ out)
{
    const int b = blockIdx.z;
    proj_body<false>(X + (size_t)b * SEQ * CH, W, bias, out, b,
                     blockIdx.x * 64, blockIdx.y * 64);
}

// ---------------- flash attention: fragment-space gumbel softmax -----------------------
// Qs/Ks/Su use the k-pair interleaved layout (ld=72) so each mma fragment pair is one
// LDS.64, conflict-free. Vs stays k-major (plain). 3 CTAs/SM.
__global__ __launch_bounds__(256, 3) void attn_mma(
    const float* __restrict__ Q, const float* __restrict__ K,
    const float* __restrict__ V, float* __restrict__ out)
{
    extern __shared__ uint32_t sm[];
    uint32_t* Qs = sm;                       // [64][72] interleaved tf32
    uint32_t* Ks = sm + 4608;                // [64][72] interleaved tf32
    uint32_t* Vs = sm + 9216;                // [64][72] plain k-major tf32
    uint32_t* Su = sm + 13824;               // [64][72] P interleaved tf32
    float*    l_s = (float*)(sm + 18432);    // [64] row sums

    const int b = blockIdx.z, h = blockIdx.y, n0 = blockIdx.x * 64;
    const int t = threadIdx.x, w = t >> 5, lane = t & 31;
    const int wm = w >> 1, wn = w & 1;
    const int g = lane >> 2, tig = lane & 3;
    const int p0 = ((tig & 1) << 2) + (tig >> 1);   // interleave pos of logical col 2*tig

    const float* Qg = Q + (((size_t)b * NH + h) * SEQ + n0) * HD;
    const float* Kg = K + ((size_t)b * NH + h) * SEQ * HD;
    const float* Vg = V + ((size_t)b * NH + h) * SEQ * HD;

    // Q prologue: interleaved k-pair store
    #pragma unroll
    for (int q = 0; q < 2; q++) {
        int i = q * 256 + t; int r = i >> 3; int d8 = (i & 7) * 8;
        const float* qp = &Qg[r * HD + d8];
        float4 q0 = *(const float4*)qp;
        float4 q1 = *(const float4*)(qp + 4);
        uint4 s;
        s.x = f2tf(q0.x); s.y = f2tf(q1.x); s.z = f2tf(q0.y); s.w = f2tf(q1.y);
        *(uint4*)&Qs[r * 72 + d8] = s;
        s.x = f2tf(q0.z); s.y = f2tf(q1.z); s.z = f2tf(q0.w); s.w = f2tf(q1.w);
        *(uint4*)&Qs[r * 72 + d8 + 4] = s;
    }
    if (t < 64) l_s[t] = 0.f;

    float acc_o[4][4];
    #pragma unroll
    for (int nt = 0; nt < 4; nt++)
        #pragma unroll
        for (int q = 0; q < 4; q++) acc_o[nt][q] = 0.f;

    const int r0 = wm * 16 + g;
    const int r1 = r0 + 8;
    const uint32_t bh = (uint32_t)(b * NH + h);
    const uint32_t base0 = ((bh << 11) + (uint32_t)(n0 + r0)) << 11;
    const uint32_t base1 = base0 + (8u << 11);
    float lr0 = 0.f, lr1 = 0.f;

    for (int k0 = 0; k0 < SEQ; k0 += 64) {
        __syncthreads();   // prev tile's readers done with Ks/Vs/Su
        #pragma unroll
        for (int q = 0; q < 2; q++) {
            int i = q * 256 + t; int r = i >> 3; int d8 = (i & 7) * 8;
            const float* kp = &Kg[(size_t)(k0 + r) * HD + d8];
            float4 k0v = *(const float4*)kp;
            float4 k1v = *(const float4*)(kp + 4);
            uint4 s;
            s.x = f2tf(k0v.x); s.y = f2tf(k1v.x); s.z = f2tf(k0v.y); s.w = f2tf(k1v.y);
            *(uint4*)&Ks[r * 72 + d8] = s;
            s.x = f2tf(k0v.z); s.y = f2tf(k1v.z); s.z = f2tf(k0v.w); s.w = f2tf(k1v.w);
            *(uint4*)&Ks[r * 72 + d8 + 4] = s;
            const float* vp = &Vg[(size_t)(k0 + r) * HD + d8];
            float4 v0v = *(const float4*)vp;
            float4 v1v = *(const float4*)(vp + 4);
            s.x = f2tf(v0v.x); s.y = f2tf(v0v.y); s.z = f2tf(v0v.z); s.w = f2tf(v0v.w);
            *(uint4*)&Vs[r * 72 + d8] = s;
            s.x = f2tf(v1v.x); s.y = f2tf(v1v.y); s.z = f2tf(v1v.z); s.w = f2tf(v1v.w);
            *(uint4*)&Vs[r * 72 + d8 + 4] = s;
        }
        __syncthreads();

        // --- S = Q K^T on fragments (paired LDS.64) ---
        float acc_s[4][4];
        #pragma unroll
        for (int nt = 0; nt < 4; nt++)
            #pragma unroll
            for (int q = 0; q < 4; q++) acc_s[nt][q] = 0.f;
        #pragma unroll
        for (int ks = 0; ks < 8; ks++) {
            const int kb = ks * 8 + 2 * tig;
            const int m = wm * 16;
            uint2 a0 = *(uint2*)&Qs[(m + g) * 72 + kb];      // (a0, a2)
            uint2 a1 = *(uint2*)&Qs[(m + g + 8) * 72 + kb];  // (a1, a3)
            #pragma unroll
            for (int nt = 0; nt < 4; nt++) {
                uint2 bb = *(uint2*)&Ks[(wn * 32 + nt * 8 + g) * 72 + kb];
                mma8(acc_s[nt][0], acc_s[nt][1], acc_s[nt][2], acc_s[nt][3],
                     a0.x, a1.x, a0.y, a1.y, bb.x, bb.y);
            }
        }

        // --- fragment-space gumbel weights: w = exp2(s*SC2) * rcp(-log u) ---
        #pragma unroll
        for (int nt = 0; nt < 4; nt++) {
            const int cb = wn * 32 + nt * 8;
            const uint32_t c0 = (uint32_t)(cb + 2 * tig);
            const uint32_t i00 = base0 + (uint32_t)k0 + c0;
            const uint32_t i10 = base1 + (uint32_t)k0 + c0;
            float t00 = neglog_u(tf_bits(i00));
            float t01 = neglog_u(tf_bits(i00 + 1u));
            float t10 = neglog_u(tf_bits(i10));
            float t11 = neglog_u(tf_bits(i10 + 1u));
            float w00 = ex2(acc_s[nt][0] * SC2) * frcp(t00);
            float w01 = ex2(acc_s[nt][1] * SC2) * frcp(t01);
            float w10 = ex2(acc_s[nt][2] * SC2) * frcp(t10);
            float w11 = ex2(acc_s[nt][3] * SC2) * frcp(t11);
            lr0 += w00 + w01;
            lr1 += w10 + w11;
            // scatter into interleaved positions (col c -> cb + pos(c&7))
            Su[r0 * 72 + cb + p0]     = f2tf(w00);
            Su[r0 * 72 + cb + p0 + 2] = f2tf(w01);
            Su[r1 * 72 + cb + p0]     = f2tf(w10);
            Su[r1 * 72 + cb + p0 + 2] = f2tf(w11);
        }
        // pair barrier: both wn halves of this wm row-group finished writing Su rows
        asm volatile("bar.sync %0, 64;" :: "r"(1 + wm) : "memory");

        // --- O += P V ---
        #pragma unroll
        for (int ks = 0; ks < 8; ks++) {
            const int kb = ks * 8 + 2 * tig;
            const int m = wm * 16;
            uint2 a0 = *(uint2*)&Su[(m + g) * 72 + kb];
            uint2 a1 = *(uint2*)&Su[(m + g + 8) * 72 + kb];
            #pragma unroll
            for (int nt = 0; nt < 4; nt++) {
                const int n = wn * 32 + nt * 8 + g;
                uint32_t b0 = Vs[(ks * 8 + tig) * 72 + n];
                uint32_t b1 = Vs[(ks * 8 + tig + 4) * 72 + n];
                mma8(acc_o[nt][0], acc_o[nt][1], acc_o[nt][2], acc_o[nt][3],
                     a0.x, a1.x, a0.y, a1.y, b0, b1);
            }
        }
    }

    // --- reduce row sums: 4 tig-lanes per row, then across wn via smem atomics ---
    lr0 += __shfl_xor_sync(0xffffffffu, lr0, 1);
    lr0 += __shfl_xor_sync(0xffffffffu, lr0, 2);
    lr1 += __shfl_xor_sync(0xffffffffu, lr1, 1);
    lr1 += __shfl_xor_sync(0xffffffffu, lr1, 2);
    if (tig == 0) {
        atomicAdd(&l_s[r0], lr0);
        atomicAdd(&l_s[r1], lr1);
    }
    __syncthreads();

    // --- epilogue: normalize, write [B, N, C] with c = h*64 + d ---
    float inv0 = 1.0f / l_s[r0];
    float inv1 = 1.0f / l_s[r1];
    #pragma unroll
    for (int nt = 0; nt < 4; nt++) {
        int d = wn * 32 + nt * 8 + 2 * tig;
        *(float2*)&out[((size_t)b * SEQ + n0 + r0) * CH + h * HD + d] =
            make_float2(acc_o[nt][0] * inv0, acc_o[nt][1] * inv0);
        *(float2*)&out[((size_t)b * SEQ + n0 + r1) * CH + h * HD + d] =
            make_float2(acc_o[nt][2] * inv1, acc_o[nt][3] * inv1);
    }
}

// ---------------- launch ----------------------------------------------------------------
extern "C" void kernel_launch(void* const* d_in, const int* in_sizes, int n_in,
                              void* d_out, int out_size)
{
    (void)in_sizes; (void)n_in; (void)out_size;
    const float* x  = (const float*)d_in[0];
    const float* y  = (const float*)d_in[1];
    const float* z  = (const float*)d_in[2];
    const float* Wq = (const float*)d_in[3];
    const float* bq = (const float*)d_in[4];
    const float* Wk = (const float*)d_in[5];
    const float* bk = (const float*)d_in[6];
    const float* Wv = (const float*)d_in[7];
    const float* bv = (const float*)d_in[8];
    const float* Wo = (const float*)d_in[9];
    const float* bo = (const float*)d_in[10];
    float* out = (float*)d_out;

    float *qp, *kp, *vp, *ap;
    cudaGetSymbolAddress((void**)&qp, g_Q);
    cudaGetSymbolAddress((void**)&kp, g_K);
    cudaGetSymbolAddress((void**)&vp, g_V);
    cudaGetSymbolAddress((void**)&ap, g_attn);

    dim3 pb(256);
    dim3 qkvg(SEQ / 64, CH / 64, NB * 3);
    proj_qkv<<<qkvg, pb>>>(x, y, z, Wq, bq, Wk, bk, Wv, bv, qp, kp, vp);

    const int SMEM = (18432 + 64) * 4;  // 73984 B
    cudaFuncSetAttribute(attn_mma, cudaFuncAttributeMaxDynamicSharedMemorySize, SMEM);
    dim3 ag(SEQ / 64, NH, NB);
    attn_mma<<<ag, pb, SMEM>>>(qp, kp, vp, ap);

    dim3 pg(SEQ / 64, CH / 64, NB);
    proj_out_k<<<pg, pb>>>(ap, Wo, bo, out);
}

// round 6
// speedup vs baseline: 1.0210x; 1.0210x over previous
#include <cuda_runtime.h>
#include <stdint.h>

#define NB 4
#define SEQ 2048
#define CH 512
#define NH 8
#define HD 64
#define SCALE 0.125f
// SCALE * log2(e)
#define SC2 0.18033688011112042f

// ---------------- device scratch (allocation-free rule: static globals) ----------------
__device__ float g_Q[(size_t)NB * NH * SEQ * HD];
__device__ float g_K[(size_t)NB * NH * SEQ * HD];
__device__ float g_V[(size_t)NB * NH * SEQ * HD];
__device__ float g_attn[(size_t)NB * SEQ * CH];

// ---------------- helpers ---------------------------------------------------------------
__device__ __forceinline__ uint32_t f2tf(float f) {
    uint32_t r;
    asm("cvt.rna.tf32.f32 %0, %1;" : "=r"(r) : "f"(f));
    return r;
}

__device__ __forceinline__ float ex2(float x) {
    float r;
    asm("ex2.approx.ftz.f32 %0, %1;" : "=f"(r) : "f"(x));
    return r;
}

__device__ __forceinline__ float frcp(float x) {
    float r;
    asm("rcp.approx.ftz.f32 %0, %1;" : "=f"(r) : "f"(x));
    return r;
}

__device__ __forceinline__ void mma8(float& d0, float& d1, float& d2, float& d3,
                                     uint32_t a0, uint32_t a1, uint32_t a2, uint32_t a3,
                                     uint32_t b0, uint32_t b1) {
    asm volatile(
        "mma.sync.aligned.m16n8k8.row.col.f32.tf32.tf32.f32 "
        "{%0,%1,%2,%3},{%4,%5,%6,%7},{%8,%9},{%0,%1,%2,%3};"
        : "+f"(d0), "+f"(d1), "+f"(d2), "+f"(d3)
        : "r"(a0), "r"(a1), "r"(a2), "r"(a3), "r"(b0), "r"(b1));
}

// ---------------- JAX threefry2x32, partitionable: bits for flat index ------------------
__device__ __forceinline__ uint32_t tf_bits(uint32_t idx) {
    const uint32_t ks0 = 0u, ks1 = 42u, ks2 = 0x1BD11BF0u;
    uint32_t x0 = ks0;
    uint32_t x1 = idx + ks1;
#define TF_R(r) { x0 += x1; x1 = __funnelshift_l(x1, x1, (r)); x1 ^= x0; }
    TF_R(13) TF_R(15) TF_R(26) TF_R(6)   x0 += ks1; x1 += ks2 + 1u;
    TF_R(17) TF_R(29) TF_R(16) TF_R(24)  x0 += ks2; x1 += ks0 + 2u;
    TF_R(13) TF_R(15) TF_R(26) TF_R(6)   x0 += ks0; x1 += ks1 + 3u;
    TF_R(17) TF_R(29) TF_R(16) TF_R(24)  x0 += ks1; x1 += ks2 + 4u;
    TF_R(13) TF_R(15) TF_R(26) TF_R(6)   x0 += ks2; x1 += ks0 + 5u;
#undef TF_R
    return x0 ^ x1;
}

// ---------------- hybrid -log(u): MUFU lg2 fast path + exact series near u->1 ----------
__device__ __forceinline__ float neglog_u(uint32_t bits) {
    float v = __uint_as_float((bits >> 9) | 0x3f800000u);  // [1,2)
    float u = v - 1.0f;                                    // exact
    float l;
    asm("lg2.approx.ftz.f32 %0, %1;" : "=f"(l) : "f"(u));
    float t1 = -0.6931471805599453f * l;
    float d = 2.0f - v;                                    // = 1-u, exact
    float t2 = d * fmaf(d, fmaf(d, 0.3333333333f, 0.5f), 1.0f);
    return (d < 0.0078125f) ? t2 : t1;
}

// ---------------- projection GEMM body: 128x128 tile, BK=32, double-buffered smem ------
// Same tile/layout as the proven R4 kernel (ld=36, 2x4 warp grid, warp tile 64x32);
// double buffering removes one barrier per k-step and stretches the prefetch window.
template <bool HEADSPLIT>
__device__ __forceinline__ void proj_body(
    const float* __restrict__ Xb, const float* __restrict__ W,
    const float* __restrict__ bias, float* __restrict__ out,
    int b, int n0, int j0)
{
    extern __shared__ uint32_t psm[];   // As[2][128*36] | Ws[2][128*36] = 73728 B
    const int t  = threadIdx.x;
    const int w  = t >> 5, lane = t & 31;
    const int wm = w & 1, wn = w >> 1;
    const int g  = lane >> 2, tig = lane & 3;

    float acc[4][4][4] = {};

    float4 pa[4], pw[4];
    #pragma unroll
    for (int p = 0; p < 4; p++) {
        int i = p * 256 + t; int r = i >> 3; int c4 = (i & 7) * 4;
        pa[p] = *(const float4*)&Xb[(size_t)(n0 + r) * CH + c4];
        pw[p] = *(const float4*)&W[(size_t)(j0 + r) * CH + c4];
    }

    for (int kk = 0; kk < 16; kk++) {
        uint32_t* As = psm + (kk & 1) * 4608;
        uint32_t* Ws = psm + 9216 + (kk & 1) * 4608;
        #pragma unroll
        for (int p = 0; p < 4; p++) {
            int i = p * 256 + t; int r = i >> 3; int c4 = (i & 7) * 4;
            As[r * 36 + c4 + 0] = f2tf(pa[p].x);
            As[r * 36 + c4 + 1] = f2tf(pa[p].y);
            As[r * 36 + c4 + 2] = f2tf(pa[p].z);
            As[r * 36 + c4 + 3] = f2tf(pa[p].w);
            Ws[r * 36 + c4 + 0] = f2tf(pw[p].x);
            Ws[r * 36 + c4 + 1] = f2tf(pw[p].y);
            Ws[r * 36 + c4 + 2] = f2tf(pw[p].z);
            Ws[r * 36 + c4 + 3] = f2tf(pw[p].w);
        }
        __syncthreads();
        if (kk < 15) {
            #pragma unroll
            for (int p = 0; p < 4; p++) {
                int i = p * 256 + t; int r = i >> 3; int c4 = (i & 7) * 4;
                pa[p] = *(const float4*)&Xb[(size_t)(n0 + r) * CH + (kk + 1) * 32 + c4];
                pw[p] = *(const float4*)&W[(size_t)(j0 + r) * CH + (kk + 1) * 32 + c4];
            }
        }
        #pragma unroll
        for (int ks = 0; ks < 4; ks++) {
            const int kb = ks * 8;
            uint32_t af[4][4], bf[4][2];
            #pragma unroll
            for (int mt = 0; mt < 4; mt++) {
                int m = wm * 64 + mt * 16;
                af[mt][0] = As[(m + g) * 36 + kb + tig];
                af[mt][1] = As[(m + g + 8) * 36 + kb + tig];
                af[mt][2] = As[(m + g) * 36 + kb + tig + 4];
                af[mt][3] = As[(m + g + 8) * 36 + kb + tig + 4];
            }
            #pragma unroll
            for (int nt = 0; nt < 4; nt++) {
                int n = wn * 32 + nt * 8;
                bf[nt][0] = Ws[(n + g) * 36 + kb + tig];
                bf[nt][1] = Ws[(n + g) * 36 + kb + tig + 4];
            }
            #pragma unroll
            for (int mt = 0; mt < 4; mt++)
                #pragma unroll
                for (int nt = 0; nt < 4; nt++)
                    mma8(acc[mt][nt][0], acc[mt][nt][1], acc[mt][nt][2], acc[mt][nt][3],
                         af[mt][0], af[mt][1], af[mt][2], af[mt][3],
                         bf[nt][0], bf[nt][1]);
        }
    }

    #pragma unroll
    for (int mt = 0; mt < 4; mt++) {
        int n = n0 + wm * 64 + mt * 16 + g;
        #pragma unroll
        for (int nt = 0; nt < 4; nt++) {
            int j = j0 + wn * 32 + nt * 8 + 2 * tig;
            float2 bj = *(const float2*)&bias[j];
            float2 v0 = make_float2(acc[mt][nt][0] + bj.x, acc[mt][nt][1] + bj.y);
            float2 v1 = make_float2(acc[mt][nt][2] + bj.x, acc[mt][nt][3] + bj.y);
            if (HEADSPLIT) {
                size_t base = (((size_t)b * NH + (j >> 6)) * SEQ) * HD + (j & 63);
                *(float2*)&out[base + (size_t)n * HD]       = v0;
                *(float2*)&out[base + (size_t)(n + 8) * HD] = v1;
            } else {
                *(float2*)&out[((size_t)b * SEQ + n) * CH + j]     = v0;
                *(float2*)&out[((size_t)b * SEQ + n + 8) * CH + j] = v1;
            }
        }
    }
}

__global__ __launch_bounds__(256, 2) void proj_qkv(
    const float* __restrict__ x, const float* __restrict__ y, const float* __restrict__ z,
    const float* __restrict__ Wq, const float* __restrict__ bq,
    const float* __restrict__ Wk, const float* __restrict__ bk,
    const float* __restrict__ Wv, const float* __restrict__ bv,
    float* __restrict__ oq, float* __restrict__ ok, float* __restrict__ ov)
{
    const int b     = blockIdx.z & 3;
    const int which = blockIdx.z >> 2;
    const float* X    = (which == 0) ? x  : (which == 1) ? y  : z;
    const float* W    = (which == 0) ? Wq : (which == 1) ? Wk : Wv;
    const float* bias = (which == 0) ? bq : (which == 1) ? bk : bv;
    float* out        = (which == 0) ? oq : (which == 1) ? ok : ov;
    proj_body<true>(X + (size_t)b * SEQ * CH, W, bias, out, b,
                    blockIdx.x * 128, blockIdx.y * 128);
}

__global__ __launch_bounds__(256, 2) void proj_out_k(
    const float* __restrict__ X, const float* __restrict__ W,
    const float* __restrict__ bias, float* __restrict__ out)
{
    const int b = blockIdx.z;
    proj_body<false>(X + (size_t)b * SEQ * CH, W, bias, out, b,
                     blockIdx.x * 128, blockIdx.y * 128);
}

// ---------------- flash attention: fragment-space gumbel softmax (R4 layout) -----------
// Delta vs R4: next tile's K/V global loads are issued after the softmax (acc_s dead),
// hiding L2 latency behind the PV mma + barriers instead of exposing it between syncs.
__global__ __launch_bounds__(256, 3) void attn_mma(
    const float* __restrict__ Q, const float* __restrict__ K,
    const float* __restrict__ V, float* __restrict__ out)
{
    extern __shared__ uint32_t sm[];
    uint32_t* Qs = sm;                       // [64][68] tf32
    uint32_t* Ks = sm + 4352;                // [64][68] tf32
    uint32_t* Vs = sm + 8704;                // [64][72] tf32
    uint32_t* Su = sm + 13312;               // [64][68] P (tf32 bits)
    float*    l_s = (float*)(sm + 17664);    // [64] row sums

    const int b = blockIdx.z, h = blockIdx.y, n0 = blockIdx.x * 64;
    const int t = threadIdx.x, w = t >> 5, lane = t & 31;
    const int wm = w >> 1, wn = w & 1;
    const int g = lane >> 2, tig = lane & 3;

    const float* Qg = Q + (((size_t)b * NH + h) * SEQ + n0) * HD;
    const float* Kg = K + ((size_t)b * NH + h) * SEQ * HD;
    const float* Vg = V + ((size_t)b * NH + h) * SEQ * HD;

    #pragma unroll
    for (int p = 0; p < 4; p++) {
        int i = p * 256 + t; int r = i >> 4; int c4 = (i & 15) * 4;
        float4 v = *(const float4*)&Qg[r * HD + c4];
        Qs[r * 68 + c4 + 0] = f2tf(v.x);
        Qs[r * 68 + c4 + 1] = f2tf(v.y);
        Qs[r * 68 + c4 + 2] = f2tf(v.z);
        Qs[r * 68 + c4 + 3] = f2tf(v.w);
    }
    if (t < 64) l_s[t] = 0.f;

    // initial K/V prefetch (tile k0 = 0)
    float4 kpf[4], vpf[4];
    #pragma unroll
    for (int p = 0; p < 4; p++) {
        int i = p * 256 + t; int r = i >> 4; int c4 = (i & 15) * 4;
        kpf[p] = *(const float4*)&Kg[(size_t)r * HD + c4];
        vpf[p] = *(const float4*)&Vg[(size_t)r * HD + c4];
    }

    float acc_o[4][4];
    #pragma unroll
    for (int nt = 0; nt < 4; nt++)
        #pragma unroll
        for (int q = 0; q < 4; q++) acc_o[nt][q] = 0.f;

    const int r0 = wm * 16 + g;
    const int r1 = r0 + 8;
    const uint32_t bh = (uint32_t)(b * NH + h);
    const uint32_t base0 = ((bh << 11) + (uint32_t)(n0 + r0)) << 11;
    const uint32_t base1 = base0 + (8u << 11);
    float lr0 = 0.f, lr1 = 0.f;

    for (int k0 = 0; k0 < SEQ; k0 += 64) {
        __syncthreads();   // prev tile's mma readers done with Ks/Vs/Su
        #pragma unroll
        for (int p = 0; p < 4; p++) {
            int i = p * 256 + t; int r = i >> 4; int c4 = (i & 15) * 4;
            Ks[r * 68 + c4 + 0] = f2tf(kpf[p].x);
            Ks[r * 68 + c4 + 1] = f2tf(kpf[p].y);
            Ks[r * 68 + c4 + 2] = f2tf(kpf[p].z);
            Ks[r * 68 + c4 + 3] = f2tf(kpf[p].w);
            Vs[r * 72 + c4 + 0] = f2tf(vpf[p].x);
            Vs[r * 72 + c4 + 1] = f2tf(vpf[p].y);
            Vs[r * 72 + c4 + 2] = f2tf(vpf[p].z);
            Vs[r * 72 + c4 + 3] = f2tf(vpf[p].w);
        }
        __syncthreads();

        // --- S = Q K^T on fragments ---
        float acc_s[4][4];
        #pragma unroll
        for (int nt = 0; nt < 4; nt++)
            #pragma unroll
            for (int q = 0; q < 4; q++) acc_s[nt][q] = 0.f;
        #pragma unroll
        for (int ks = 0; ks < 8; ks++) {
            const int kb = ks * 8;
            const int m = wm * 16;
            uint32_t a0 = Qs[(m + g) * 68 + kb + tig];
            uint32_t a1 = Qs[(m + g + 8) * 68 + kb + tig];
            uint32_t a2 = Qs[(m + g) * 68 + kb + tig + 4];
            uint32_t a3 = Qs[(m + g + 8) * 68 + kb + tig + 4];
            #pragma unroll
            for (int nt = 0; nt < 4; nt++) {
                int n = wn * 32 + nt * 8;
                uint32_t b0 = Ks[(n + g) * 68 + kb + tig];
                uint32_t b1 = Ks[(n + g) * 68 + kb + tig + 4];
                mma8(acc_s[nt][0], acc_s[nt][1], acc_s[nt][2], acc_s[nt][3],
                     a0, a1, a2, a3, b0, b1);
            }
        }

        // --- fragment-space gumbel weights: w = exp2(s*SC2) * rcp(-log u) ---
        #pragma unroll
        for (int nt = 0; nt < 4; nt++) {
            const uint32_t c0 = (uint32_t)(wn * 32 + nt * 8 + 2 * tig);
            const uint32_t i00 = base0 + (uint32_t)k0 + c0;
            const uint32_t i10 = base1 + (uint32_t)k0 + c0;
            float t00 = neglog_u(tf_bits(i00));
            float t01 = neglog_u(tf_bits(i00 + 1u));
            float t10 = neglog_u(tf_bits(i10));
            float t11 = neglog_u(tf_bits(i10 + 1u));
            float w00 = ex2(acc_s[nt][0] * SC2) * frcp(t00);
            float w01 = ex2(acc_s[nt][1] * SC2) * frcp(t01);
            float w10 = ex2(acc_s[nt][2] * SC2) * frcp(t10);
            float w11 = ex2(acc_s[nt][3] * SC2) * frcp(t11);
            lr0 += w00 + w01;
            lr1 += w10 + w11;
            uint2 p0 = make_uint2(f2tf(w00), f2tf(w01));
            uint2 p1 = make_uint2(f2tf(w10), f2tf(w11));
            *(uint2*)&Su[r0 * 68 + c0] = p0;
            *(uint2*)&Su[r1 * 68 + c0] = p1;
        }

        // --- prefetch next tile's K/V (acc_s dead; hidden behind pair-bar + PV mma) ---
        if (k0 + 64 < SEQ) {
            #pragma unroll
            for (int p = 0; p < 4; p++) {
                int i = p * 256 + t; int r = i >> 4; int c4 = (i & 15) * 4;
                kpf[p] = *(const float4*)&Kg[(size_t)(k0 + 64 + r) * HD + c4];
                vpf[p] = *(const float4*)&Vg[(size_t)(k0 + 64 + r) * HD + c4];
            }
        }

        // pair barrier: both wn halves of this wm row-group finished writing Su rows
        asm volatile("bar.sync %0, 64;" :: "r"(1 + wm) : "memory");

        // --- O += P V (A rows are this pair's own Su rows) ---
        #pragma unroll
        for (int ks = 0; ks < 8; ks++) {
            const int kb = ks * 8;
            const int m = wm * 16;
            uint32_t a0 = Su[(m + g) * 68 + kb + tig];
            uint32_t a1 = Su[(m + g + 8) * 68 + kb + tig];
            uint32_t a2 = Su[(m + g) * 68 + kb + tig + 4];
            uint32_t a3 = Su[(m + g + 8) * 68 + kb + tig + 4];
            #pragma unroll
            for (int nt = 0; nt < 4; nt++) {
                int n = wn * 32 + nt * 8;
                uint32_t b0 = Vs[(kb + tig) * 72 + n + g];
                uint32_t b1 = Vs[(kb + tig + 4) * 72 + n + g];
                mma8(acc_o[nt][0], acc_o[nt][1], acc_o[nt][2], acc_o[nt][3],
                     a0, a1, a2, a3, b0, b1);
            }
        }
    }

    // --- reduce row sums: 4 tig-lanes per row, then across wn via smem atomics ---
    lr0 += __shfl_xor_sync(0xffffffffu, lr0, 1);
    lr0 += __shfl_xor_sync(0xffffffffu, lr0, 2);
    lr1 += __shfl_xor_sync(0xffffffffu, lr1, 1);
    lr1 += __shfl_xor_sync(0xffffffffu, lr1, 2);
    if (tig == 0) {
        atomicAdd(&l_s[r0], lr0);
        atomicAdd(&l_s[r1], lr1);
    }
    __syncthreads();

    // --- epilogue: normalize, write [B, N, C] with c = h*64 + d ---
    float inv0 = 1.0f / l_s[r0];
    float inv1 = 1.0f / l_s[r1];
    #pragma unroll
    for (int nt = 0; nt < 4; nt++) {
        int d = wn * 32 + nt * 8 + 2 * tig;
        *(float2*)&out[((size_t)b * SEQ + n0 + r0) * CH + h * HD + d] =
            make_float2(acc_o[nt][0] * inv0, acc_o[nt][1] * inv0);
        *(float2*)&out[((size_t)b * SEQ + n0 + r1) * CH + h * HD + d] =
            make_float2(acc_o[nt][2] * inv1, acc_o[nt][3] * inv1);
    }
}

// ---------------- launch ----------------------------------------------------------------
extern "C" void kernel_launch(void* const* d_in, const int* in_sizes, int n_in,
                              void* d_out, int out_size)
{
    (void)in_sizes; (void)n_in; (void)out_size;
    const float* x  = (const float*)d_in[0];
    const float* y  = (const float*)d_in[1];
    const float* z  = (const float*)d_in[2];
    const float* Wq = (const float*)d_in[3];
    const float* bq = (const float*)d_in[4];
    const float* Wk = (const float*)d_in[5];
    const float* bk = (const float*)d_in[6];
    const float* Wv = (const float*)d_in[7];
    const float* bv = (const float*)d_in[8];
    const float* Wo = (const float*)d_in[9];
    const float* bo = (const float*)d_in[10];
    float* out = (float*)d_out;

    float *qp, *kp, *vp, *ap;
    cudaGetSymbolAddress((void**)&qp, g_Q);
    cudaGetSymbolAddress((void**)&kp, g_K);
    cudaGetSymbolAddress((void**)&vp, g_V);
    cudaGetSymbolAddress((void**)&ap, g_attn);

    const int PSMEM = 4 * 4608 * 4;     // 73728 B (double-buffered A+W)
    cudaFuncSetAttribute(proj_qkv, cudaFuncAttributeMaxDynamicSharedMemorySize, PSMEM);
    cudaFuncSetAttribute(proj_out_k, cudaFuncAttributeMaxDynamicSharedMemorySize, PSMEM);

    dim3 pb(256);
    dim3 qkvg(SEQ / 128, CH / 128, NB * 3);
    proj_qkv<<<qkvg, pb, PSMEM>>>(x, y, z, Wq, bq, Wk, bk, Wv, bv, qp, kp, vp);

    const int SMEM = (17664 + 64) * 4;  // 70912 B
    cudaFuncSetAttribute(attn_mma, cudaFuncAttributeMaxDynamicSharedMemorySize, SMEM);
    dim3 ag(SEQ / 64, NH, NB);
    attn_mma<<<ag, pb, SMEM>>>(qp, kp, vp, ap);

    dim3 pg(SEQ / 128, CH / 128, NB);
    proj_out_k<<<pg, pb, PSMEM>>>(ap, Wo, bo, out);
}

// round 7
// speedup vs baseline: 1.0589x; 1.0372x over previous
#include <cuda_runtime.h>
#include <stdint.h>

#define NB 4
#define SEQ 2048
#define CH 512
#define NH 8
#define HD 64
// SCALE * log2(e)
#define SC2 0.18033688011112042f

// ---------------- device scratch (allocation-free rule: static globals) ----------------
// Q/K/V are stored as tf32 bit patterns (converted once in the projection epilogue).
__device__ uint32_t g_Q[(size_t)NB * NH * SEQ * HD];
__device__ uint32_t g_K[(size_t)NB * NH * SEQ * HD];
__device__ uint32_t g_V[(size_t)NB * NH * SEQ * HD];
__device__ float    g_attn[(size_t)NB * SEQ * CH];

// ---------------- helpers ---------------------------------------------------------------
__device__ __forceinline__ uint32_t f2tf(float f) {
    uint32_t r;
    asm("cvt.rna.tf32.f32 %0, %1;" : "=r"(r) : "f"(f));
    return r;
}

__device__ __forceinline__ float ex2(float x) {
    float r;
    asm("ex2.approx.ftz.f32 %0, %1;" : "=f"(r) : "f"(x));
    return r;
}

__device__ __forceinline__ float frcp(float x) {
    float r;
    asm("rcp.approx.ftz.f32 %0, %1;" : "=f"(r) : "f"(x));
    return r;
}

__device__ __forceinline__ void mma8(float& d0, float& d1, float& d2, float& d3,
                                     uint32_t a0, uint32_t a1, uint32_t a2, uint32_t a3,
                                     uint32_t b0, uint32_t b1) {
    asm volatile(
        "mma.sync.aligned.m16n8k8.row.col.f32.tf32.tf32.f32 "
        "{%0,%1,%2,%3},{%4,%5,%6,%7},{%8,%9},{%0,%1,%2,%3};"
        : "+f"(d0), "+f"(d1), "+f"(d2), "+f"(d3)
        : "r"(a0), "r"(a1), "r"(a2), "r"(a3), "r"(b0), "r"(b1));
}

__device__ __forceinline__ void cp16(uint32_t* smem_dst, const uint32_t* gmem_src) {
    uint32_t sa = (uint32_t)__cvta_generic_to_shared(smem_dst);
    asm volatile("cp.async.cg.shared.global [%0], [%1], 16;" :: "r"(sa), "l"(gmem_src));
}
#define CP_COMMIT() asm volatile("cp.async.commit_group;" ::: "memory")
#define CP_WAIT0()  asm volatile("cp.async.wait_group 0;"  ::: "memory")

// ---------------- JAX threefry2x32, partitionable: bits for flat index ------------------
__device__ __forceinline__ uint32_t tf_bits(uint32_t idx) {
    const uint32_t ks0 = 0u, ks1 = 42u, ks2 = 0x1BD11BF0u;
    uint32_t x0 = ks0;
    uint32_t x1 = idx + ks1;
#define TF_R(r) { x0 += x1; x1 = __funnelshift_l(x1, x1, (r)); x1 ^= x0; }
    TF_R(13) TF_R(15) TF_R(26) TF_R(6)   x0 += ks1; x1 += ks2 + 1u;
    TF_R(17) TF_R(29) TF_R(16) TF_R(24)  x0 += ks2; x1 += ks0 + 2u;
    TF_R(13) TF_R(15) TF_R(26) TF_R(6)   x0 += ks0; x1 += ks1 + 3u;
    TF_R(17) TF_R(29) TF_R(16) TF_R(24)  x0 += ks1; x1 += ks2 + 4u;
    TF_R(13) TF_R(15) TF_R(26) TF_R(6)   x0 += ks2; x1 += ks0 + 5u;
#undef TF_R
    return x0 ^ x1;
}

// ---------------- hybrid -log(u): MUFU lg2 fast path + exact series near u->1 ----------
__device__ __forceinline__ float neglog_u(uint32_t bits) {
    float v = __uint_as_float((bits >> 9) | 0x3f800000u);  // [1,2)
    float u = v - 1.0f;                                    // exact
    float l;
    asm("lg2.approx.ftz.f32 %0, %1;" : "=f"(l) : "f"(u));
    float t1 = -0.6931471805599453f * l;
    float d = 2.0f - v;                                    // = 1-u, exact
    float t2 = d * fmaf(d, fmaf(d, 0.3333333333f, 0.5f), 1.0f);
    return (d < 0.0078125f) ? t2 : t1;
}

// ---------------- projection GEMM body: 128x128 tile, BK=32 (proven R4 shape) ----------
// HEADSPLIT=true writes tf32 BIT PATTERNS (uint32) in head-split layout; false writes f32.
template <bool HEADSPLIT>
__device__ __forceinline__ void proj_body(
    const float* __restrict__ Xb, const float* __restrict__ W,
    const float* __restrict__ bias, void* __restrict__ outv,
    int b, int n0, int j0)
{
    __shared__ uint32_t As[128 * 36];
    __shared__ uint32_t Ws[128 * 36];
    const int t  = threadIdx.x;
    const int w  = t >> 5, lane = t & 31;
    const int wm = w & 1, wn = w >> 1;
    const int g  = lane >> 2, tig = lane & 3;

    float acc[4][4][4] = {};

    float4 pa[4], pw[4];
    #pragma unroll
    for (int p = 0; p < 4; p++) {
        int i = p * 256 + t; int r = i >> 3; int c4 = (i & 7) * 4;
        pa[p] = *(const float4*)&Xb[(size_t)(n0 + r) * CH + c4];
        pw[p] = *(const float4*)&W[(size_t)(j0 + r) * CH + c4];
    }

    for (int k0 = 0; k0 < CH; k0 += 32) {
        __syncthreads();
        #pragma unroll
        for (int p = 0; p < 4; p++) {
            int i = p * 256 + t; int r = i >> 3; int c4 = (i & 7) * 4;
            As[r * 36 + c4 + 0] = f2tf(pa[p].x);
            As[r * 36 + c4 + 1] = f2tf(pa[p].y);
            As[r * 36 + c4 + 2] = f2tf(pa[p].z);
            As[r * 36 + c4 + 3] = f2tf(pa[p].w);
            Ws[r * 36 + c4 + 0] = f2tf(pw[p].x);
            Ws[r * 36 + c4 + 1] = f2tf(pw[p].y);
            Ws[r * 36 + c4 + 2] = f2tf(pw[p].z);
            Ws[r * 36 + c4 + 3] = f2tf(pw[p].w);
        }
        __syncthreads();
        if (k0 + 32 < CH) {
            #pragma unroll
            for (int p = 0; p < 4; p++) {
                int i = p * 256 + t; int r = i >> 3; int c4 = (i & 7) * 4;
                pa[p] = *(const float4*)&Xb[(size_t)(n0 + r) * CH + k0 + 32 + c4];
                pw[p] = *(const float4*)&W[(size_t)(j0 + r) * CH + k0 + 32 + c4];
            }
        }
        #pragma unroll
        for (int ks = 0; ks < 4; ks++) {
            const int kb = ks * 8;
            uint32_t af[4][4], bf[4][2];
            #pragma unroll
            for (int mt = 0; mt < 4; mt++) {
                int m = wm * 64 + mt * 16;
                af[mt][0] = As[(m + g) * 36 + kb + tig];
                af[mt][1] = As[(m + g + 8) * 36 + kb + tig];
                af[mt][2] = As[(m + g) * 36 + kb + tig + 4];
                af[mt][3] = As[(m + g + 8) * 36 + kb + tig + 4];
            }
            #pragma unroll
            for (int nt = 0; nt < 4; nt++) {
                int n = wn * 32 + nt * 8;
                bf[nt][0] = Ws[(n + g) * 36 + kb + tig];
                bf[nt][1] = Ws[(n + g) * 36 + kb + tig + 4];
            }
            #pragma unroll
            for (int mt = 0; mt < 4; mt++)
                #pragma unroll
                for (int nt = 0; nt < 4; nt++)
                    mma8(acc[mt][nt][0], acc[mt][nt][1], acc[mt][nt][2], acc[mt][nt][3],
                         af[mt][0], af[mt][1], af[mt][2], af[mt][3],
                         bf[nt][0], bf[nt][1]);
        }
    }

    #pragma unroll
    for (int mt = 0; mt < 4; mt++) {
        int n = n0 + wm * 64 + mt * 16 + g;
        #pragma unroll
        for (int nt = 0; nt < 4; nt++) {
            int j = j0 + wn * 32 + nt * 8 + 2 * tig;
            float2 bj = *(const float2*)&bias[j];
            if (HEADSPLIT) {
                uint32_t* out = (uint32_t*)outv;
                uint2 v0 = make_uint2(f2tf(acc[mt][nt][0] + bj.x), f2tf(acc[mt][nt][1] + bj.y));
                uint2 v1 = make_uint2(f2tf(acc[mt][nt][2] + bj.x), f2tf(acc[mt][nt][3] + bj.y));
                size_t base = (((size_t)b * NH + (j >> 6)) * SEQ) * HD + (j & 63);
                *(uint2*)&out[base + (size_t)n * HD]       = v0;
                *(uint2*)&out[base + (size_t)(n + 8) * HD] = v1;
            } else {
                float* out = (float*)outv;
                *(float2*)&out[((size_t)b * SEQ + n) * CH + j] =
                    make_float2(acc[mt][nt][0] + bj.x, acc[mt][nt][1] + bj.y);
                *(float2*)&out[((size_t)b * SEQ + n + 8) * CH + j] =
                    make_float2(acc[mt][nt][2] + bj.x, acc[mt][nt][3] + bj.y);
            }
        }
    }
}

__global__ __launch_bounds__(256, 2) void proj_qkv(
    const float* __restrict__ x, const float* __restrict__ y, const float* __restrict__ z,
    const float* __restrict__ Wq, const float* __restrict__ bq,
    const float* __restrict__ Wk, const float* __restrict__ bk,
    const float* __restrict__ Wv, const float* __restrict__ bv,
    uint32_t* __restrict__ oq, uint32_t* __restrict__ ok, uint32_t* __restrict__ ov)
{
    const int b     = blockIdx.z & 3;
    const int which = blockIdx.z >> 2;
    const float* X    = (which == 0) ? x  : (which == 1) ? y  : z;
    const float* W    = (which == 0) ? Wq : (which == 1) ? Wk : Wv;
    const float* bias = (which == 0) ? bq : (which == 1) ? bk : bv;
    uint32_t* out     = (which == 0) ? oq : (which == 1) ? ok : ov;
    proj_body<true>(X + (size_t)b * SEQ * CH, W, bias, out, b,
                    blockIdx.x * 128, blockIdx.y * 128);
}

__global__ __launch_bounds__(256, 2) void proj_out_k(
    const float* __restrict__ X, const float* __restrict__ W,
    const float* __restrict__ bias, float* __restrict__ out)
{
    const int b = blockIdx.z;
    proj_body<false>(X + (size_t)b * SEQ * CH, W, bias, out, b,
                     blockIdx.x * 128, blockIdx.y * 128);
}

// ---------------- flash attention: cp.async K/V pipeline + fragment gumbel softmax -----
// Q/K/V arrive pre-converted to tf32 bits. K/V staged via cp.async into double-buffered
// smem (no registers, latency overlapped); one __syncthreads per tile. Q fragments
// hoisted to registers once. 2 CTAs/SM (smem-limited), 128 regs available.
__global__ __launch_bounds__(256, 2) void attn_mma(
    const uint32_t* __restrict__ Q, const uint32_t* __restrict__ K,
    const uint32_t* __restrict__ V, float* __restrict__ out)
{
    extern __shared__ uint32_t sm[];
    uint32_t* Qs  = sm;                      // [64][68]
    // Ks bufs at 4352, 8704; Vs bufs at 13056, 17664; Su at 22272; l_s at 26624
    uint32_t* Su  = sm + 22272;              // [64][68] P (tf32 bits)
    float*    l_s = (float*)(sm + 26624);    // [64] row sums

    const int b = blockIdx.z, h = blockIdx.y, n0 = blockIdx.x * 64;
    const int t = threadIdx.x, w = t >> 5, lane = t & 31;
    const int wm = w >> 1, wn = w & 1;
    const int g = lane >> 2, tig = lane & 3;

    const uint32_t* Qg = Q + (((size_t)b * NH + h) * SEQ + n0) * HD;
    const uint32_t* Kg = K + ((size_t)b * NH + h) * SEQ * HD;
    const uint32_t* Vg = V + ((size_t)b * NH + h) * SEQ * HD;

    // staging geometry: thread -> (row rs, 16-word column chunk cb)
    const int rs = t >> 2;
    const int cb = (t & 3) * 16;

    // prologue: async-copy Q and tile-0 K/V
    #pragma unroll
    for (int c = 0; c < 16; c += 4)
        cp16(&Qs[rs * 68 + cb + c], Qg + (size_t)rs * HD + cb + c);
    #pragma unroll
    for (int c = 0; c < 16; c += 4) {
        cp16(&sm[4352 + rs * 68 + cb + c], Kg + (size_t)rs * HD + cb + c);
        cp16(&sm[13056 + rs * 72 + cb + c], Vg + (size_t)rs * HD + cb + c);
    }
    CP_COMMIT();
    if (t < 64) l_s[t] = 0.f;
    CP_WAIT0();
    __syncthreads();

    // hoist Q fragments for this warp's m-rows (constant across all key tiles)
    uint32_t qf[8][4];
    #pragma unroll
    for (int ks = 0; ks < 8; ks++) {
        const int kb = ks * 8;
        const int m = wm * 16;
        qf[ks][0] = Qs[(m + g) * 68 + kb + tig];
        qf[ks][1] = Qs[(m + g + 8) * 68 + kb + tig];
        qf[ks][2] = Qs[(m + g) * 68 + kb + tig + 4];
        qf[ks][3] = Qs[(m + g + 8) * 68 + kb + tig + 4];
    }

    float acc_o[4][4];
    #pragma unroll
    for (int nt = 0; nt < 4; nt++)
        #pragma unroll
        for (int q = 0; q < 4; q++) acc_o[nt][q] = 0.f;

    const int r0 = wm * 16 + g;
    const int r1 = r0 + 8;
    const uint32_t bh = (uint32_t)(b * NH + h);
    const uint32_t base0 = ((bh << 11) + (uint32_t)(n0 + r0)) << 11;
    const uint32_t base1 = base0 + (8u << 11);
    float lr0 = 0.f, lr1 = 0.f;

    for (int n = 0; n < 32; n++) {
        uint32_t* Kb = sm + 4352 + (n & 1) * 4352;
        uint32_t* Vb = sm + 13056 + (n & 1) * 4608;
        const int k0 = n * 64;

        // prefetch next tile into the other buffer (its last readers finished
        // before the end-of-iteration barrier of tile n-1)
        if (n < 31) {
            const uint32_t* Kn = Kg + (size_t)(k0 + 64) * HD;
            const uint32_t* Vn = Vg + (size_t)(k0 + 64) * HD;
            uint32_t* Kd = sm + 4352 + ((n + 1) & 1) * 4352;
            uint32_t* Vd = sm + 13056 + ((n + 1) & 1) * 4608;
            #pragma unroll
            for (int c = 0; c < 16; c += 4) {
                cp16(&Kd[rs * 68 + cb + c], Kn + (size_t)rs * HD + cb + c);
                cp16(&Vd[rs * 72 + cb + c], Vn + (size_t)rs * HD + cb + c);
            }
            CP_COMMIT();
        }

        // --- S = Q K^T on fragments ---
        float acc_s[4][4];
        #pragma unroll
        for (int nt = 0; nt < 4; nt++)
            #pragma unroll
            for (int q = 0; q < 4; q++) acc_s[nt][q] = 0.f;
        #pragma unroll
        for (int ks = 0; ks < 8; ks++) {
            const int kb = ks * 8;
            #pragma unroll
            for (int nt = 0; nt < 4; nt++) {
                int nn = wn * 32 + nt * 8;
                uint32_t b0 = Kb[(nn + g) * 68 + kb + tig];
                uint32_t b1 = Kb[(nn + g) * 68 + kb + tig + 4];
                mma8(acc_s[nt][0], acc_s[nt][1], acc_s[nt][2], acc_s[nt][3],
                     qf[ks][0], qf[ks][1], qf[ks][2], qf[ks][3], b0, b1);
            }
        }

        // --- fragment-space gumbel weights: w = exp2(s*SC2) * rcp(-log u) ---
        #pragma unroll
        for (int nt = 0; nt < 4; nt++) {
            const uint32_t c0 = (uint32_t)(wn * 32 + nt * 8 + 2 * tig);
            const uint32_t i00 = base0 + (uint32_t)k0 + c0;
            const uint32_t i10 = base1 + (uint32_t)k0 + c0;
            float t00 = neglog_u(tf_bits(i00));
            float t01 = neglog_u(tf_bits(i00 + 1u));
            float t10 = neglog_u(tf_bits(i10));
            float t11 = neglog_u(tf_bits(i10 + 1u));
            float w00 = ex2(acc_s[nt][0] * SC2) * frcp(t00);
            float w01 = ex2(acc_s[nt][1] * SC2) * frcp(t01);
            float w10 = ex2(acc_s[nt][2] * SC2) * frcp(t10);
            float w11 = ex2(acc_s[nt][3] * SC2) * frcp(t11);
            lr0 += w00 + w01;
            lr1 += w10 + w11;
            uint2 p0 = make_uint2(f2tf(w00), f2tf(w01));
            uint2 p1 = make_uint2(f2tf(w10), f2tf(w11));
            *(uint2*)&Su[r0 * 68 + c0] = p0;
            *(uint2*)&Su[r1 * 68 + c0] = p1;
        }
        // pair barrier: both wn halves of this wm row-group finished writing Su rows
        asm volatile("bar.sync %0, 64;" :: "r"(1 + wm) : "memory");

        // --- O += P V (A rows are this pair's own Su rows) ---
        #pragma unroll
        for (int ks = 0; ks < 8; ks++) {
            const int kb = ks * 8;
            const int m = wm * 16;
            uint32_t a0 = Su[(m + g) * 68 + kb + tig];
            uint32_t a1 = Su[(m + g + 8) * 68 + kb + tig];
            uint32_t a2 = Su[(m + g) * 68 + kb + tig + 4];
            uint32_t a3 = Su[(m + g + 8) * 68 + kb + tig + 4];
            #pragma unroll
            for (int nt = 0; nt < 4; nt++) {
                int nn = wn * 32 + nt * 8;
                uint32_t b0 = Vb[(kb + tig) * 72 + nn + g];
                uint32_t b1 = Vb[(kb + tig + 4) * 72 + nn + g];
                mma8(acc_o[nt][0], acc_o[nt][1], acc_o[nt][2], acc_o[nt][3],
                     a0, a1, a2, a3, b0, b1);
            }
        }

        // single end-of-tile barrier: next tile's copies landed AND everyone is
        // done reading this tile's buffers + Su
        if (n < 31) {
            CP_WAIT0();
            __syncthreads();
        }
    }

    // --- reduce row sums: 4 tig-lanes per row, then across wn via smem atomics ---
    lr0 += __shfl_xor_sync(0xffffffffu, lr0, 1);
    lr0 += __shfl_xor_sync(0xffffffffu, lr0, 2);
    lr1 += __shfl_xor_sync(0xffffffffu, lr1, 1);
    lr1 += __shfl_xor_sync(0xffffffffu, lr1, 2);
    if (tig == 0) {
        atomicAdd(&l_s[r0], lr0);
        atomicAdd(&l_s[r1], lr1);
    }
    __syncthreads();

    // --- epilogue: normalize, write [B, N, C] with c = h*64 + d ---
    float inv0 = 1.0f / l_s[r0];
    float inv1 = 1.0f / l_s[r1];
    #pragma unroll
    for (int nt = 0; nt < 4; nt++) {
        int d = wn * 32 + nt * 8 + 2 * tig;
        *(float2*)&out[((size_t)b * SEQ + n0 + r0) * CH + h * HD + d] =
            make_float2(acc_o[nt][0] * inv0, acc_o[nt][1] * inv0);
        *(float2*)&out[((size_t)b * SEQ + n0 + r1) * CH + h * HD + d] =
            make_float2(acc_o[nt][2] * inv1, acc_o[nt][3] * inv1);
    }
}

// ---------------- launch ----------------------------------------------------------------
extern "C" void kernel_launch(void* const* d_in, const int* in_sizes, int n_in,
                              void* d_out, int out_size)
{
    (void)in_sizes; (void)n_in; (void)out_size;
    const float* x  = (const float*)d_in[0];
    const float* y  = (const float*)d_in[1];
    const float* z  = (const float*)d_in[2];
    const float* Wq = (const float*)d_in[3];
    const float* bq = (const float*)d_in[4];
    const float* Wk = (const float*)d_in[5];
    const float* bk = (const float*)d_in[6];
    const float* Wv = (const float*)d_in[7];
    const float* bv = (const float*)d_in[8];
    const float* Wo = (const float*)d_in[9];
    const float* bo = (const float*)d_in[10];
    float* out = (float*)d_out;

    uint32_t *qp, *kp, *vp;
    float *ap;
    cudaGetSymbolAddress((void**)&qp, g_Q);
    cudaGetSymbolAddress((void**)&kp, g_K);
    cudaGetSymbolAddress((void**)&vp, g_V);
    cudaGetSymbolAddress((void**)&ap, g_attn);

    dim3 pb(256);
    dim3 qkvg(SEQ / 128, CH / 128, NB * 3);
    proj_qkv<<<qkvg, pb>>>(x, y, z, Wq, bq, Wk, bk, Wv, bv, qp, kp, vp);

    const int SMEM = 26688 * 4;  // 106752 B
    cudaFuncSetAttribute(attn_mma, cudaFuncAttributeMaxDynamicSharedMemorySize, SMEM);
    dim3 ag(SEQ / 64, NH, NB);
    attn_mma<<<ag, pb, SMEM>>>(qp, kp, vp, ap);

    dim3 pg(SEQ / 128, CH / 128, NB);
    proj_out_k<<<pg, pb>>>(ap, Wo, bo, out);
}

// round 8
// speedup vs baseline: 1.1479x; 1.0840x over previous
#include <cuda_runtime.h>
#include <stdint.h>

#define NB 4
#define SEQ 2048
#define CH 512
#define NH 8
#define HD 64
// SCALE * log2(e)
#define SC2 0.18033688011112042f

// ---------------- device scratch (allocation-free rule: static globals) ----------------
// Q/K/V are stored as tf32 bit patterns (converted once in the projection epilogue).
__device__ uint32_t g_Q[(size_t)NB * NH * SEQ * HD];
__device__ uint32_t g_K[(size_t)NB * NH * SEQ * HD];
__device__ uint32_t g_V[(size_t)NB * NH * SEQ * HD];
__device__ float    g_attn[(size_t)NB * SEQ * CH];

// ---------------- helpers ---------------------------------------------------------------
__device__ __forceinline__ uint32_t f2tf(float f) {
    uint32_t r;
    asm("cvt.rna.tf32.f32 %0, %1;" : "=r"(r) : "f"(f));
    return r;
}

__device__ __forceinline__ float ex2(float x) {
    float r;
    asm("ex2.approx.ftz.f32 %0, %1;" : "=f"(r) : "f"(x));
    return r;
}

__device__ __forceinline__ float frcp(float x) {
    float r;
    asm("rcp.approx.ftz.f32 %0, %1;" : "=f"(r) : "f"(x));
    return r;
}

__device__ __forceinline__ void mma8(float& d0, float& d1, float& d2, float& d3,
                                     uint32_t a0, uint32_t a1, uint32_t a2, uint32_t a3,
                                     uint32_t b0, uint32_t b1) {
    asm volatile(
        "mma.sync.aligned.m16n8k8.row.col.f32.tf32.tf32.f32 "
        "{%0,%1,%2,%3},{%4,%5,%6,%7},{%8,%9},{%0,%1,%2,%3};"
        : "+f"(d0), "+f"(d1), "+f"(d2), "+f"(d3)
        : "r"(a0), "r"(a1), "r"(a2), "r"(a3), "r"(b0), "r"(b1));
}

// ---------------- JAX threefry2x32, partitionable: bits for flat index ------------------
__device__ __forceinline__ uint32_t tf_bits(uint32_t idx) {
    const uint32_t ks0 = 0u, ks1 = 42u, ks2 = 0x1BD11BF0u;
    uint32_t x0 = ks0;
    uint32_t x1 = idx + ks1;
#define TF_R(r) { x0 += x1; x1 = __funnelshift_l(x1, x1, (r)); x1 ^= x0; }
    TF_R(13) TF_R(15) TF_R(26) TF_R(6)   x0 += ks1; x1 += ks2 + 1u;
    TF_R(17) TF_R(29) TF_R(16) TF_R(24)  x0 += ks2; x1 += ks0 + 2u;
    TF_R(13) TF_R(15) TF_R(26) TF_R(6)   x0 += ks0; x1 += ks1 + 3u;
    TF_R(17) TF_R(29) TF_R(16) TF_R(24)  x0 += ks1; x1 += ks2 + 4u;
    TF_R(13) TF_R(15) TF_R(26) TF_R(6)   x0 += ks2; x1 += ks0 + 5u;
#undef TF_R
    return x0 ^ x1;
}

// ---------------- hybrid -log(u): MUFU lg2 fast path + exact series near u->1 ----------
__device__ __forceinline__ float neglog_u(uint32_t bits) {
    float v = __uint_as_float((bits >> 9) | 0x3f800000u);  // [1,2)
    float u = v - 1.0f;                                    // exact
    float l;
    asm("lg2.approx.ftz.f32 %0, %1;" : "=f"(l) : "f"(u));
    float t1 = -0.6931471805599453f * l;
    float d = 2.0f - v;                                    // = 1-u, exact
    float t2 = d * fmaf(d, fmaf(d, 0.3333333333f, 0.5f), 1.0f);
    return (d < 0.0078125f) ? t2 : t1;
}

// ---------------- projection GEMM body: 128x128 tile, BK=32 (proven R4 shape) ----------
// HEADSPLIT=true writes tf32 BIT PATTERNS (uint32) in head-split layout; false writes f32.
template <bool HEADSPLIT>
__device__ __forceinline__ void proj_body(
    const float* __restrict__ Xb, const float* __restrict__ W,
    const float* __restrict__ bias, void* __restrict__ outv,
    int b, int n0, int j0)
{
    __shared__ uint32_t As[128 * 36];
    __shared__ uint32_t Ws[128 * 36];
    const int t  = threadIdx.x;
    const int w  = t >> 5, lane = t & 31;
    const int wm = w & 1, wn = w >> 1;
    const int g  = lane >> 2, tig = lane & 3;

    float acc[4][4][4] = {};

    float4 pa[4], pw[4];
    #pragma unroll
    for (int p = 0; p < 4; p++) {
        int i = p * 256 + t; int r = i >> 3; int c4 = (i & 7) * 4;
        pa[p] = *(const float4*)&Xb[(size_t)(n0 + r) * CH + c4];
        pw[p] = *(const float4*)&W[(size_t)(j0 + r) * CH + c4];
    }

    for (int k0 = 0; k0 < CH; k0 += 32) {
        __syncthreads();
        #pragma unroll
        for (int p = 0; p < 4; p++) {
            int i = p * 256 + t; int r = i >> 3; int c4 = (i & 7) * 4;
            As[r * 36 + c4 + 0] = f2tf(pa[p].x);
            As[r * 36 + c4 + 1] = f2tf(pa[p].y);
            As[r * 36 + c4 + 2] = f2tf(pa[p].z);
            As[r * 36 + c4 + 3] = f2tf(pa[p].w);
            Ws[r * 36 + c4 + 0] = f2tf(pw[p].x);
            Ws[r * 36 + c4 + 1] = f2tf(pw[p].y);
            Ws[r * 36 + c4 + 2] = f2tf(pw[p].z);
            Ws[r * 36 + c4 + 3] = f2tf(pw[p].w);
        }
        __syncthreads();
        if (k0 + 32 < CH) {
            #pragma unroll
            for (int p = 0; p < 4; p++) {
                int i = p * 256 + t; int r = i >> 3; int c4 = (i & 7) * 4;
                pa[p] = *(const float4*)&Xb[(size_t)(n0 + r) * CH + k0 + 32 + c4];
                pw[p] = *(const float4*)&W[(size_t)(j0 + r) * CH + k0 + 32 + c4];
            }
        }
        #pragma unroll
        for (int ks = 0; ks < 4; ks++) {
            const int kb = ks * 8;
            uint32_t af[4][4], bf[4][2];
            #pragma unroll
            for (int mt = 0; mt < 4; mt++) {
                int m = wm * 64 + mt * 16;
                af[mt][0] = As[(m + g) * 36 + kb + tig];
                af[mt][1] = As[(m + g + 8) * 36 + kb + tig];
                af[mt][2] = As[(m + g) * 36 + kb + tig + 4];
                af[mt][3] = As[(m + g + 8) * 36 + kb + tig + 4];
            }
            #pragma unroll
            for (int nt = 0; nt < 4; nt++) {
                int n = wn * 32 + nt * 8;
                bf[nt][0] = Ws[(n + g) * 36 + kb + tig];
                bf[nt][1] = Ws[(n + g) * 36 + kb + tig + 4];
            }
            #pragma unroll
            for (int mt = 0; mt < 4; mt++)
                #pragma unroll
                for (int nt = 0; nt < 4; nt++)
                    mma8(acc[mt][nt][0], acc[mt][nt][1], acc[mt][nt][2], acc[mt][nt][3],
                         af[mt][0], af[mt][1], af[mt][2], af[mt][3],
                         bf[nt][0], bf[nt][1]);
        }
    }

    #pragma unroll
    for (int mt = 0; mt < 4; mt++) {
        int n = n0 + wm * 64 + mt * 16 + g;
        #pragma unroll
        for (int nt = 0; nt < 4; nt++) {
            int j = j0 + wn * 32 + nt * 8 + 2 * tig;
            float2 bj = *(const float2*)&bias[j];
            if (HEADSPLIT) {
                uint32_t* out = (uint32_t*)outv;
                uint2 v0 = make_uint2(f2tf(acc[mt][nt][0] + bj.x), f2tf(acc[mt][nt][1] + bj.y));
                uint2 v1 = make_uint2(f2tf(acc[mt][nt][2] + bj.x), f2tf(acc[mt][nt][3] + bj.y));
                size_t base = (((size_t)b * NH + (j >> 6)) * SEQ) * HD + (j & 63);
                *(uint2*)&out[base + (size_t)n * HD]       = v0;
                *(uint2*)&out[base + (size_t)(n + 8) * HD] = v1;
            } else {
                float* out = (float*)outv;
                *(float2*)&out[((size_t)b * SEQ + n) * CH + j] =
                    make_float2(acc[mt][nt][0] + bj.x, acc[mt][nt][1] + bj.y);
                *(float2*)&out[((size_t)b * SEQ + n + 8) * CH + j] =
                    make_float2(acc[mt][nt][2] + bj.x, acc[mt][nt][3] + bj.y);
            }
        }
    }
}

__global__ __launch_bounds__(256, 2) void proj_qkv(
    const float* __restrict__ x, const float* __restrict__ y, const float* __restrict__ z,
    const float* __restrict__ Wq, const float* __restrict__ bq,
    const float* __restrict__ Wk, const float* __restrict__ bk,
    const float* __restrict__ Wv, const float* __restrict__ bv,
    uint32_t* __restrict__ oq, uint32_t* __restrict__ ok, uint32_t* __restrict__ ov)
{
    const int b     = blockIdx.z & 3;
    const int which = blockIdx.z >> 2;
    const float* X    = (which == 0) ? x  : (which == 1) ? y  : z;
    const float* W    = (which == 0) ? Wq : (which == 1) ? Wk : Wv;
    const float* bias = (which == 0) ? bq : (which == 1) ? bk : bv;
    uint32_t* out     = (which == 0) ? oq : (which == 1) ? ok : ov;
    proj_body<true>(X + (size_t)b * SEQ * CH, W, bias, out, b,
                    blockIdx.x * 128, blockIdx.y * 128);
}

__global__ __launch_bounds__(256, 2) void proj_out_k(
    const float* __restrict__ X, const float* __restrict__ W,
    const float* __restrict__ bias, float* __restrict__ out)
{
    const int b = blockIdx.z;
    proj_body<false>(X + (size_t)b * SEQ * CH, W, bias, out, b,
                     blockIdx.x * 128, blockIdx.y * 128);
}

// ---------------- flash attention: R4 structure + pre-converted tf32 + uint4 staging ---
// Q/K/V arrive as tf32 bits, so per-tile staging is 8 LDG.128 + 8 STS.128 (no CVTs,
// no scalar stores). Same 3 CTAs/SM, same barriers, same math as the 754us R4 kernel.
__global__ __launch_bounds__(256, 3) void attn_mma(
    const uint32_t* __restrict__ Q, const uint32_t* __restrict__ K,
    const uint32_t* __restrict__ V, float* __restrict__ out)
{
    extern __shared__ uint32_t sm[];
    uint32_t* Qs = sm;                       // [64][68]
    uint32_t* Ks = sm + 4352;                // [64][68]
    uint32_t* Vs = sm + 8704;                // [64][72]
    uint32_t* Su = sm + 13312;               // [64][68] P (tf32 bits)
    float*    l_s = (float*)(sm + 17664);    // [64] row sums

    const int b = blockIdx.z, h = blockIdx.y, n0 = blockIdx.x * 64;
    const int t = threadIdx.x, w = t >> 5, lane = t & 31;
    const int wm = w >> 1, wn = w & 1;
    const int g = lane >> 2, tig = lane & 3;

    const uint32_t* Qg = Q + (((size_t)b * NH + h) * SEQ + n0) * HD;
    const uint32_t* Kg = K + ((size_t)b * NH + h) * SEQ * HD;
    const uint32_t* Vg = V + ((size_t)b * NH + h) * SEQ * HD;

    #pragma unroll
    for (int p = 0; p < 4; p++) {
        int i = p * 256 + t; int r = i >> 4; int c4 = (i & 15) * 4;
        *(uint4*)&Qs[r * 68 + c4] = *(const uint4*)&Qg[(size_t)r * HD + c4];
    }
    if (t < 64) l_s[t] = 0.f;

    float acc_o[4][4];
    #pragma unroll
    for (int nt = 0; nt < 4; nt++)
        #pragma unroll
        for (int q = 0; q < 4; q++) acc_o[nt][q] = 0.f;

    const int r0 = wm * 16 + g;
    const int r1 = r0 + 8;
    const uint32_t bh = (uint32_t)(b * NH + h);
    const uint32_t base0 = ((bh << 11) + (uint32_t)(n0 + r0)) << 11;
    const uint32_t base1 = base0 + (8u << 11);
    float lr0 = 0.f, lr1 = 0.f;

    for (int k0 = 0; k0 < SEQ; k0 += 64) {
        __syncthreads();   // prev tile's mma readers done with Ks/Vs/Su
        #pragma unroll
        for (int p = 0; p < 4; p++) {
            int i = p * 256 + t; int r = i >> 4; int c4 = (i & 15) * 4;
            *(uint4*)&Ks[r * 68 + c4] = *(const uint4*)&Kg[(size_t)(k0 + r) * HD + c4];
            *(uint4*)&Vs[r * 72 + c4] = *(const uint4*)&Vg[(size_t)(k0 + r) * HD + c4];
        }
        __syncthreads();

        // --- S = Q K^T on fragments ---
        float acc_s[4][4];
        #pragma unroll
        for (int nt = 0; nt < 4; nt++)
            #pragma unroll
            for (int q = 0; q < 4; q++) acc_s[nt][q] = 0.f;
        #pragma unroll
        for (int ks = 0; ks < 8; ks++) {
            const int kb = ks * 8;
            const int m = wm * 16;
            uint32_t a0 = Qs[(m + g) * 68 + kb + tig];
            uint32_t a1 = Qs[(m + g + 8) * 68 + kb + tig];
            uint32_t a2 = Qs[(m + g) * 68 + kb + tig + 4];
            uint32_t a3 = Qs[(m + g + 8) * 68 + kb + tig + 4];
            #pragma unroll
            for (int nt = 0; nt < 4; nt++) {
                int n = wn * 32 + nt * 8;
                uint32_t b0 = Ks[(n + g) * 68 + kb + tig];
                uint32_t b1 = Ks[(n + g) * 68 + kb + tig + 4];
                mma8(acc_s[nt][0], acc_s[nt][1], acc_s[nt][2], acc_s[nt][3],
                     a0, a1, a2, a3, b0, b1);
            }
        }

        // --- fragment-space gumbel weights: w = exp2(s*SC2) * rcp(-log u) ---
        #pragma unroll
        for (int nt = 0; nt < 4; nt++) {
            const uint32_t c0 = (uint32_t)(wn * 32 + nt * 8 + 2 * tig);
            const uint32_t i00 = base0 + (uint32_t)k0 + c0;
            const uint32_t i10 = base1 + (uint32_t)k0 + c0;
            float t00 = neglog_u(tf_bits(i00));
            float t01 = neglog_u(tf_bits(i00 + 1u));
            float t10 = neglog_u(tf_bits(i10));
            float t11 = neglog_u(tf_bits(i10 + 1u));
            float w00 = ex2(acc_s[nt][0] * SC2) * frcp(t00);
            float w01 = ex2(acc_s[nt][1] * SC2) * frcp(t01);
            float w10 = ex2(acc_s[nt][2] * SC2) * frcp(t10);
            float w11 = ex2(acc_s[nt][3] * SC2) * frcp(t11);
            lr0 += w00 + w01;
            lr1 += w10 + w11;
            uint2 p0 = make_uint2(f2tf(w00), f2tf(w01));
            uint2 p1 = make_uint2(f2tf(w10), f2tf(w11));
            *(uint2*)&Su[r0 * 68 + c0] = p0;
            *(uint2*)&Su[r1 * 68 + c0] = p1;
        }
        // pair barrier: both wn halves of this wm row-group finished writing Su rows
        asm volatile("bar.sync %0, 64;" :: "r"(1 + wm) : "memory");

        // --- O += P V (A rows are this pair's own Su rows) ---
        #pragma unroll
        for (int ks = 0; ks < 8; ks++) {
            const int kb = ks * 8;
            const int m = wm * 16;
            uint32_t a0 = Su[(m + g) * 68 + kb + tig];
            uint32_t a1 = Su[(m + g + 8) * 68 + kb + tig];
            uint32_t a2 = Su[(m + g) * 68 + kb + tig + 4];
            uint32_t a3 = Su[(m + g + 8) * 68 + kb + tig + 4];
            #pragma unroll
            for (int nt = 0; nt < 4; nt++) {
                int n = wn * 32 + nt * 8;
                uint32_t b0 = Vs[(kb + tig) * 72 + n + g];
                uint32_t b1 = Vs[(kb + tig + 4) * 72 + n + g];
                mma8(acc_o[nt][0], acc_o[nt][1], acc_o[nt][2], acc_o[nt][3],
                     a0, a1, a2, a3, b0, b1);
            }
        }
    }

    // --- reduce row sums: 4 tig-lanes per row, then across wn via smem atomics ---
    lr0 += __shfl_xor_sync(0xffffffffu, lr0, 1);
    lr0 += __shfl_xor_sync(0xffffffffu, lr0, 2);
    lr1 += __shfl_xor_sync(0xffffffffu, lr1, 1);
    lr1 += __shfl_xor_sync(0xffffffffu, lr1, 2);
    if (tig == 0) {
        atomicAdd(&l_s[r0], lr0);
        atomicAdd(&l_s[r1], lr1);
    }
    __syncthreads();

    // --- epilogue: normalize, write [B, N, C] with c = h*64 + d ---
    float inv0 = 1.0f / l_s[r0];
    float inv1 = 1.0f / l_s[r1];
    #pragma unroll
    for (int nt = 0; nt < 4; nt++) {
        int d = wn * 32 + nt * 8 + 2 * tig;
        *(float2*)&out[((size_t)b * SEQ + n0 + r0) * CH + h * HD + d] =
            make_float2(acc_o[nt][0] * inv0, acc_o[nt][1] * inv0);
        *(float2*)&out[((size_t)b * SEQ + n0 + r1) * CH + h * HD + d] =
            make_float2(acc_o[nt][2] * inv1, acc_o[nt][3] * inv1);
    }
}

// ---------------- launch ----------------------------------------------------------------
extern "C" void kernel_launch(void* const* d_in, const int* in_sizes, int n_in,
                              void* d_out, int out_size)
{
    (void)in_sizes; (void)n_in; (void)out_size;
    const float* x  = (const float*)d_in[0];
    const float* y  = (const float*)d_in[1];
    const float* z  = (const float*)d_in[2];
    const float* Wq = (const float*)d_in[3];
    const float* bq = (const float*)d_in[4];
    const float* Wk = (const float*)d_in[5];
    const float* bk = (const float*)d_in[6];
    const float* Wv = (const float*)d_in[7];
    const float* bv = (const float*)d_in[8];
    const float* Wo = (const float*)d_in[9];
    const float* bo = (const float*)d_in[10];
    float* out = (float*)d_out;

    uint32_t *qp, *kp, *vp;
    float *ap;
    cudaGetSymbolAddress((void**)&qp, g_Q);
    cudaGetSymbolAddress((void**)&kp, g_K);
    cudaGetSymbolAddress((void**)&vp, g_V);
    cudaGetSymbolAddress((void**)&ap, g_attn);

    dim3 pb(256);
    dim3 qkvg(SEQ / 128, CH / 128, NB * 3);
    proj_qkv<<<qkvg, pb>>>(x, y, z, Wq, bq, Wk, bk, Wv, bv, qp, kp, vp);

    const int SMEM = (17664 + 64) * 4;  // 70912 B -> 3 CTAs/SM
    cudaFuncSetAttribute(attn_mma, cudaFuncAttributeMaxDynamicSharedMemorySize, SMEM);
    dim3 ag(SEQ / 64, NH, NB);
    attn_mma<<<ag, pb, SMEM>>>(qp, kp, vp, ap);

    dim3 pg(SEQ / 128, CH / 128, NB);
    proj_out_k<<<pg, pb>>>(ap, Wo, bo, out);
}

// round 9
// speedup vs baseline: 1.1602x; 1.0107x over previous
#include <cuda_runtime.h>
#include <stdint.h>

#define NB 4
#define SEQ 2048
#define CH 512
#define NH 8
#define HD 64
// SCALE * log2(e)
#define SC2 0.18033688011112042f

// ---------------- device scratch (allocation-free rule: static globals) ----------------
// Q/K/V are stored as tf32 bit patterns (converted once in the projection epilogue).
__device__ uint32_t g_Q[(size_t)NB * NH * SEQ * HD];
__device__ uint32_t g_K[(size_t)NB * NH * SEQ * HD];
__device__ uint32_t g_V[(size_t)NB * NH * SEQ * HD];
__device__ float    g_oA[(size_t)NB * SEQ * CH];    // split-0 unnormalized O
__device__ float    g_oB[(size_t)NB * SEQ * CH];    // split-1 unnormalized O
__device__ float    g_l[(size_t)2 * NB * NH * SEQ]; // split row sums
__device__ float    g_attn[(size_t)NB * SEQ * CH];  // combined, normalized

// ---------------- helpers ---------------------------------------------------------------
__device__ __forceinline__ uint32_t f2tf(float f) {
    uint32_t r;
    asm("cvt.rna.tf32.f32 %0, %1;" : "=r"(r) : "f"(f));
    return r;
}

__device__ __forceinline__ float ex2(float x) {
    float r;
    asm("ex2.approx.ftz.f32 %0, %1;" : "=f"(r) : "f"(x));
    return r;
}

__device__ __forceinline__ float frcp(float x) {
    float r;
    asm("rcp.approx.ftz.f32 %0, %1;" : "=f"(r) : "f"(x));
    return r;
}

__device__ __forceinline__ void mma8(float& d0, float& d1, float& d2, float& d3,
                                     uint32_t a0, uint32_t a1, uint32_t a2, uint32_t a3,
                                     uint32_t b0, uint32_t b1) {
    asm volatile(
        "mma.sync.aligned.m16n8k8.row.col.f32.tf32.tf32.f32 "
        "{%0,%1,%2,%3},{%4,%5,%6,%7},{%8,%9},{%0,%1,%2,%3};"
        : "+f"(d0), "+f"(d1), "+f"(d2), "+f"(d3)
        : "r"(a0), "r"(a1), "r"(a2), "r"(a3), "r"(b0), "r"(b1));
}

// ---------------- JAX threefry2x32, partitionable: bits for flat index ------------------
__device__ __forceinline__ uint32_t tf_bits(uint32_t idx) {
    const uint32_t ks0 = 0u, ks1 = 42u, ks2 = 0x1BD11BF0u;
    uint32_t x0 = ks0;
    uint32_t x1 = idx + ks1;
#define TF_R(r) { x0 += x1; x1 = __funnelshift_l(x1, x1, (r)); x1 ^= x0; }
    TF_R(13) TF_R(15) TF_R(26) TF_R(6)   x0 += ks1; x1 += ks2 + 1u;
    TF_R(17) TF_R(29) TF_R(16) TF_R(24)  x0 += ks2; x1 += ks0 + 2u;
    TF_R(13) TF_R(15) TF_R(26) TF_R(6)   x0 += ks0; x1 += ks1 + 3u;
    TF_R(17) TF_R(29) TF_R(16) TF_R(24)  x0 += ks1; x1 += ks2 + 4u;
    TF_R(13) TF_R(15) TF_R(26) TF_R(6)   x0 += ks2; x1 += ks0 + 5u;
#undef TF_R
    return x0 ^ x1;
}

// ---------------- hybrid -log(u): MUFU lg2 fast path + exact series near u->1 ----------
__device__ __forceinline__ float neglog_u(uint32_t bits) {
    float v = __uint_as_float((bits >> 9) | 0x3f800000u);  // [1,2)
    float u = v - 1.0f;                                    // exact
    float l;
    asm("lg2.approx.ftz.f32 %0, %1;" : "=f"(l) : "f"(u));
    float t1 = -0.6931471805599453f * l;
    float d = 2.0f - v;                                    // = 1-u, exact
    float t2 = d * fmaf(d, fmaf(d, 0.3333333333f, 0.5f), 1.0f);
    return (d < 0.0078125f) ? t2 : t1;
}

// ---------------- projection GEMM body: 128x128 tile, BK=32 (proven R4 shape) ----------
// HEADSPLIT=true writes tf32 BIT PATTERNS (uint32) in head-split layout; false writes f32.
template <bool HEADSPLIT>
__device__ __forceinline__ void proj_body(
    const float* __restrict__ Xb, const float* __restrict__ W,
    const float* __restrict__ bias, void* __restrict__ outv,
    int b, int n0, int j0)
{
    __shared__ uint32_t As[128 * 36];
    __shared__ uint32_t Ws[128 * 36];
    const int t  = threadIdx.x;
    const int w  = t >> 5, lane = t & 31;
    const int wm = w & 1, wn = w >> 1;
    const int g  = lane >> 2, tig = lane & 3;

    float acc[4][4][4] = {};

    float4 pa[4], pw[4];
    #pragma unroll
    for (int p = 0; p < 4; p++) {
        int i = p * 256 + t; int r = i >> 3; int c4 = (i & 7) * 4;
        pa[p] = *(const float4*)&Xb[(size_t)(n0 + r) * CH + c4];
        pw[p] = *(const float4*)&W[(size_t)(j0 + r) * CH + c4];
    }

    for (int k0 = 0; k0 < CH; k0 += 32) {
        __syncthreads();
        #pragma unroll
        for (int p = 0; p < 4; p++) {
            int i = p * 256 + t; int r = i >> 3; int c4 = (i & 7) * 4;
            As[r * 36 + c4 + 0] = f2tf(pa[p].x);
            As[r * 36 + c4 + 1] = f2tf(pa[p].y);
            As[r * 36 + c4 + 2] = f2tf(pa[p].z);
            As[r * 36 + c4 + 3] = f2tf(pa[p].w);
            Ws[r * 36 + c4 + 0] = f2tf(pw[p].x);
            Ws[r * 36 + c4 + 1] = f2tf(pw[p].y);
            Ws[r * 36 + c4 + 2] = f2tf(pw[p].z);
            Ws[r * 36 + c4 + 3] = f2tf(pw[p].w);
        }
        __syncthreads();
        if (k0 + 32 < CH) {
            #pragma unroll
            for (int p = 0; p < 4; p++) {
                int i = p * 256 + t; int r = i >> 3; int c4 = (i & 7) * 4;
                pa[p] = *(const float4*)&Xb[(size_t)(n0 + r) * CH + k0 + 32 + c4];
                pw[p] = *(const float4*)&W[(size_t)(j0 + r) * CH + k0 + 32 + c4];
            }
        }
        #pragma unroll
        for (int ks = 0; ks < 4; ks++) {
            const int kb = ks * 8;
            uint32_t af[4][4], bf[4][2];
            #pragma unroll
            for (int mt = 0; mt < 4; mt++) {
                int m = wm * 64 + mt * 16;
                af[mt][0] = As[(m + g) * 36 + kb + tig];
                af[mt][1] = As[(m + g + 8) * 36 + kb + tig];
                af[mt][2] = As[(m + g) * 36 + kb + tig + 4];
                af[mt][3] = As[(m + g + 8) * 36 + kb + tig + 4];
            }
            #pragma unroll
            for (int nt = 0; nt < 4; nt++) {
                int n = wn * 32 + nt * 8;
                bf[nt][0] = Ws[(n + g) * 36 + kb + tig];
                bf[nt][1] = Ws[(n + g) * 36 + kb + tig + 4];
            }
            #pragma unroll
            for (int mt = 0; mt < 4; mt++)
                #pragma unroll
                for (int nt = 0; nt < 4; nt++)
                    mma8(acc[mt][nt][0], acc[mt][nt][1], acc[mt][nt][2], acc[mt][nt][3],
                         af[mt][0], af[mt][1], af[mt][2], af[mt][3],
                         bf[nt][0], bf[nt][1]);
        }
    }

    #pragma unroll
    for (int mt = 0; mt < 4; mt++) {
        int n = n0 + wm * 64 + mt * 16 + g;
        #pragma unroll
        for (int nt = 0; nt < 4; nt++) {
            int j = j0 + wn * 32 + nt * 8 + 2 * tig;
            float2 bj = *(const float2*)&bias[j];
            if (HEADSPLIT) {
                uint32_t* out = (uint32_t*)outv;
                uint2 v0 = make_uint2(f2tf(acc[mt][nt][0] + bj.x), f2tf(acc[mt][nt][1] + bj.y));
                uint2 v1 = make_uint2(f2tf(acc[mt][nt][2] + bj.x), f2tf(acc[mt][nt][3] + bj.y));
                size_t base = (((size_t)b * NH + (j >> 6)) * SEQ) * HD + (j & 63);
                *(uint2*)&out[base + (size_t)n * HD]       = v0;
                *(uint2*)&out[base + (size_t)(n + 8) * HD] = v1;
            } else {
                float* out = (float*)outv;
                *(float2*)&out[((size_t)b * SEQ + n) * CH + j] =
                    make_float2(acc[mt][nt][0] + bj.x, acc[mt][nt][1] + bj.y);
                *(float2*)&out[((size_t)b * SEQ + n + 8) * CH + j] =
                    make_float2(acc[mt][nt][2] + bj.x, acc[mt][nt][3] + bj.y);
            }
        }
    }
}

__global__ __launch_bounds__(256, 2) void proj_qkv(
    const float* __restrict__ x, const float* __restrict__ y, const float* __restrict__ z,
    const float* __restrict__ Wq, const float* __restrict__ bq,
    const float* __restrict__ Wk, const float* __restrict__ bk,
    const float* __restrict__ Wv, const float* __restrict__ bv,
    uint32_t* __restrict__ oq, uint32_t* __restrict__ ok, uint32_t* __restrict__ ov)
{
    const int b     = blockIdx.z & 3;
    const int which = blockIdx.z >> 2;
    const float* X    = (which == 0) ? x  : (which == 1) ? y  : z;
    const float* W    = (which == 0) ? Wq : (which == 1) ? Wk : Wv;
    const float* bias = (which == 0) ? bq : (which == 1) ? bk : bv;
    uint32_t* out     = (which == 0) ? oq : (which == 1) ? ok : ov;
    proj_body<true>(X + (size_t)b * SEQ * CH, W, bias, out, b,
                    blockIdx.x * 128, blockIdx.y * 128);
}

__global__ __launch_bounds__(256, 2) void proj_out_k(
    const float* __restrict__ X, const float* __restrict__ W,
    const float* __restrict__ bias, float* __restrict__ out)
{
    const int b = blockIdx.z;
    proj_body<false>(X + (size_t)b * SEQ * CH, W, bias, out, b,
                     blockIdx.x * 128, blockIdx.y * 128);
}

// ---------------- flash attention, 2-way K-split -----------------------------------------
// No-max softmax is additive, so each split CTA handles keys [1024s, 1024s+1024) and
// writes UNNORMALIZED O-partial + row-sum partial to its own buffers. 2048 CTAs ->
// wave efficiency 92% (vs 77% at 1024 CTAs / 3 per SM). Same proven R8 tile structure.
__global__ __launch_bounds__(256, 3) void attn_mma(
    const uint32_t* __restrict__ Q, const uint32_t* __restrict__ K,
    const uint32_t* __restrict__ V, float* __restrict__ outA,
    float* __restrict__ outB, float* __restrict__ lbuf)
{
    extern __shared__ uint32_t sm[];
    uint32_t* Qs = sm;                       // [64][68]
    uint32_t* Ks = sm + 4352;                // [64][68]
    uint32_t* Vs = sm + 8704;                // [64][72]
    uint32_t* Su = sm + 13312;               // [64][68] P (tf32 bits)
    float*    l_s = (float*)(sm + 17664);    // [64] row sums

    const int b = blockIdx.z & 3, s = blockIdx.z >> 2;
    const int h = blockIdx.y, n0 = blockIdx.x * 64;
    const int t = threadIdx.x, w = t >> 5, lane = t & 31;
    const int wm = w >> 1, wn = w & 1;
    const int g = lane >> 2, tig = lane & 3;

    const uint32_t* Qg = Q + (((size_t)b * NH + h) * SEQ + n0) * HD;
    const uint32_t* Kg = K + ((size_t)b * NH + h) * SEQ * HD;
    const uint32_t* Vg = V + ((size_t)b * NH + h) * SEQ * HD;

    #pragma unroll
    for (int p = 0; p < 4; p++) {
        int i = p * 256 + t; int r = i >> 4; int c4 = (i & 15) * 4;
        *(uint4*)&Qs[r * 68 + c4] = *(const uint4*)&Qg[(size_t)r * HD + c4];
    }
    if (t < 64) l_s[t] = 0.f;

    float acc_o[4][4];
    #pragma unroll
    for (int nt = 0; nt < 4; nt++)
        #pragma unroll
        for (int q = 0; q < 4; q++) acc_o[nt][q] = 0.f;

    const int r0 = wm * 16 + g;
    const int r1 = r0 + 8;
    const uint32_t bh = (uint32_t)(b * NH + h);
    const uint32_t base0 = ((bh << 11) + (uint32_t)(n0 + r0)) << 11;
    const uint32_t base1 = base0 + (8u << 11);
    float lr0 = 0.f, lr1 = 0.f;

    const int kbeg = s * (SEQ / 2);
    const int kend = kbeg + SEQ / 2;
    for (int k0 = kbeg; k0 < kend; k0 += 64) {
        __syncthreads();   // prev tile's mma readers done with Ks/Vs/Su
        #pragma unroll
        for (int p = 0; p < 4; p++) {
            int i = p * 256 + t; int r = i >> 4; int c4 = (i & 15) * 4;
            *(uint4*)&Ks[r * 68 + c4] = *(const uint4*)&Kg[(size_t)(k0 + r) * HD + c4];
            *(uint4*)&Vs[r * 72 + c4] = *(const uint4*)&Vg[(size_t)(k0 + r) * HD + c4];
        }
        __syncthreads();

        // --- S = Q K^T on fragments ---
        float acc_s[4][4];
        #pragma unroll
        for (int nt = 0; nt < 4; nt++)
            #pragma unroll
            for (int q = 0; q < 4; q++) acc_s[nt][q] = 0.f;
        #pragma unroll
        for (int ks = 0; ks < 8; ks++) {
            const int kb = ks * 8;
            const int m = wm * 16;
            uint32_t a0 = Qs[(m + g) * 68 + kb + tig];
            uint32_t a1 = Qs[(m + g + 8) * 68 + kb + tig];
            uint32_t a2 = Qs[(m + g) * 68 + kb + tig + 4];
            uint32_t a3 = Qs[(m + g + 8) * 68 + kb + tig + 4];
            #pragma unroll
            for (int nt = 0; nt < 4; nt++) {
                int n = wn * 32 + nt * 8;
                uint32_t b0 = Ks[(n + g) * 68 + kb + tig];
                uint32_t b1 = Ks[(n + g) * 68 + kb + tig + 4];
                mma8(acc_s[nt][0], acc_s[nt][1], acc_s[nt][2], acc_s[nt][3],
                     a0, a1, a2, a3, b0, b1);
            }
        }

        // --- fragment-space gumbel weights: w = exp2(s*SC2) * rcp(-log u) ---
        #pragma unroll
        for (int nt = 0; nt < 4; nt++) {
            const uint32_t c0 = (uint32_t)(wn * 32 + nt * 8 + 2 * tig);
            const uint32_t i00 = base0 + (uint32_t)k0 + c0;
            const uint32_t i10 = base1 + (uint32_t)k0 + c0;
            float t00 = neglog_u(tf_bits(i00));
            float t01 = neglog_u(tf_bits(i00 + 1u));
            float t10 = neglog_u(tf_bits(i10));
            float t11 = neglog_u(tf_bits(i10 + 1u));
            float w00 = ex2(acc_s[nt][0] * SC2) * frcp(t00);
            float w01 = ex2(acc_s[nt][1] * SC2) * frcp(t01);
            float w10 = ex2(acc_s[nt][2] * SC2) * frcp(t10);
            float w11 = ex2(acc_s[nt][3] * SC2) * frcp(t11);
            lr0 += w00 + w01;
            lr1 += w10 + w11;
            uint2 p0 = make_uint2(f2tf(w00), f2tf(w01));
            uint2 p1 = make_uint2(f2tf(w10), f2tf(w11));
            *(uint2*)&Su[r0 * 68 + c0] = p0;
            *(uint2*)&Su[r1 * 68 + c0] = p1;
        }
        // pair barrier: both wn halves of this wm row-group finished writing Su rows
        asm volatile("bar.sync %0, 64;" :: "r"(1 + wm) : "memory");

        // --- O += P V (A rows are this pair's own Su rows) ---
        #pragma unroll
        for (int ks = 0; ks < 8; ks++) {
            const int kb = ks * 8;
            const int m = wm * 16;
            uint32_t a0 = Su[(m + g) * 68 + kb + tig];
            uint32_t a1 = Su[(m + g + 8) * 68 + kb + tig];
            uint32_t a2 = Su[(m + g) * 68 + kb + tig + 4];
            uint32_t a3 = Su[(m + g + 8) * 68 + kb + tig + 4];
            #pragma unroll
            for (int nt = 0; nt < 4; nt++) {
                int n = wn * 32 + nt * 8;
                uint32_t b0 = Vs[(kb + tig) * 72 + n + g];
                uint32_t b1 = Vs[(kb + tig + 4) * 72 + n + g];
                mma8(acc_o[nt][0], acc_o[nt][1], acc_o[nt][2], acc_o[nt][3],
                     a0, a1, a2, a3, b0, b1);
            }
        }
    }

    // --- reduce row sums: 4 tig-lanes per row, then across wn via smem atomics ---
    lr0 += __shfl_xor_sync(0xffffffffu, lr0, 1);
    lr0 += __shfl_xor_sync(0xffffffffu, lr0, 2);
    lr1 += __shfl_xor_sync(0xffffffffu, lr1, 1);
    lr1 += __shfl_xor_sync(0xffffffffu, lr1, 2);
    if (tig == 0) {
        atomicAdd(&l_s[r0], lr0);
        atomicAdd(&l_s[r1], lr1);
    }
    __syncthreads();

    // --- epilogue: write UNNORMALIZED partials for this split ---
    float* Ob = s ? outB : outA;
    #pragma unroll
    for (int nt = 0; nt < 4; nt++) {
        int d = wn * 32 + nt * 8 + 2 * tig;
        *(float2*)&Ob[((size_t)b * SEQ + n0 + r0) * CH + h * HD + d] =
            make_float2(acc_o[nt][0], acc_o[nt][1]);
        *(float2*)&Ob[((size_t)b * SEQ + n0 + r1) * CH + h * HD + d] =
            make_float2(acc_o[nt][2], acc_o[nt][3]);
    }
    if (t < 64)
        lbuf[((size_t)s * NB * NH + bh) * SEQ + n0 + t] = l_s[t];
}

// ---------------- combine: out = (O0 + O1) / (l0 + l1) ---------------------------------
__global__ __launch_bounds__(128) void combine_norm(
    const float* __restrict__ A, const float* __restrict__ B,
    const float* __restrict__ l, float* __restrict__ out)
{
    const int r = blockIdx.x;              // b*SEQ + n
    const int b = r >> 11, n = r & 2047;
    const int t = threadIdx.x;
    const int h = t >> 4;
    size_t li = ((size_t)b * NH + h) * SEQ + n;
    float ls = l[li] + l[(size_t)NB * NH * SEQ + li];
    float inv = 1.0f / ls;
    size_t i = (size_t)r * CH + t * 4;
    float4 a  = *(const float4*)&A[i];
    float4 bb = *(const float4*)&B[i];
    *(float4*)&out[i] = make_float4((a.x + bb.x) * inv, (a.y + bb.y) * inv,
                                    (a.z + bb.z) * inv, (a.w + bb.w) * inv);
}

// ---------------- launch ----------------------------------------------------------------
extern "C" void kernel_launch(void* const* d_in, const int* in_sizes, int n_in,
                              void* d_out, int out_size)
{
    (void)in_sizes; (void)n_in; (void)out_size;
    const float* x  = (const float*)d_in[0];
    const float* y  = (const float*)d_in[1];
    const float* z  = (const float*)d_in[2];
    const float* Wq = (const float*)d_in[3];
    const float* bq = (const float*)d_in[4];
    const float* Wk = (const float*)d_in[5];
    const float* bk = (const float*)d_in[6];
    const float* Wv = (const float*)d_in[7];
    const float* bv = (const float*)d_in[8];
    const float* Wo = (const float*)d_in[9];
    const float* bo = (const float*)d_in[10];
    float* out = (float*)d_out;

    uint32_t *qp, *kp, *vp;
    float *oa, *ob, *lp, *ap;
    cudaGetSymbolAddress((void**)&qp, g_Q);
    cudaGetSymbolAddress((void**)&kp, g_K);
    cudaGetSymbolAddress((void**)&vp, g_V);
    cudaGetSymbolAddress((void**)&oa, g_oA);
    cudaGetSymbolAddress((void**)&ob, g_oB);
    cudaGetSymbolAddress((void**)&lp, g_l);
    cudaGetSymbolAddress((void**)&ap, g_attn);

    dim3 pb(256);
    dim3 qkvg(SEQ / 128, CH / 128, NB * 3);
    proj_qkv<<<qkvg, pb>>>(x, y, z, Wq, bq, Wk, bk, Wv, bv, qp, kp, vp);

    const int SMEM = (17664 + 64) * 4;  // 70912 B -> 3 CTAs/SM
    cudaFuncSetAttribute(attn_mma, cudaFuncAttributeMaxDynamicSharedMemorySize, SMEM);
    dim3 ag(SEQ / 64, NH, NB * 2);      // z = batch + 4*split
    attn_mma<<<ag, pb, SMEM>>>(qp, kp, vp, oa, ob, lp);

    combine_norm<<<NB * SEQ, 128>>>(oa, ob, lp, ap);

    dim3 pg(SEQ / 128, CH / 128, NB);
    proj_out_k<<<pg, pb>>>(ap, Wo, bo, out);
}